// round 1
// baseline (speedup 1.0000x reference)
#include <cuda_runtime.h>
#include <cuda_bf16.h>
#include <math.h>

// Problem constants
#define B_  8
#define N_  512
#define D_  512
#define H_  8
#define DH_ 64
#define E_  32768
#define BIASDIM_ 8
#define BN_ (B_ * N_)          // 4096 rows

// -------------------- scratch (device globals; no allocs allowed) ----------
__device__ float g_q[BN_ * D_];
__device__ float g_k[BN_ * D_];
__device__ float g_v[BN_ * D_];
__device__ float g_ctx[BN_ * D_];
__device__ float g_bias[B_ * N_ * N_];
__device__ float g_sk[B_ * N_ * H_];
__device__ float g_table[BIASDIM_];

// -------------------- generic 64x64x16 tiled fp32 GEMM ---------------------
// C[M,N] = A[M,K] * B[K,N], all row-major. 256 threads, 4x4 per thread.
__global__ void gemm_kernel(const float* __restrict__ A,
                            const float* __restrict__ Bm,
                            float* __restrict__ C,
                            int M, int N, int K) {
    __shared__ float As[16][68];   // [kk][m]
    __shared__ float Bs[16][68];   // [kk][n]
    const int tid = threadIdx.x;
    const int tx = tid & 15, ty = tid >> 4;
    const int bm = blockIdx.x * 64, bn = blockIdx.y * 64;

    float acc[4][4];
#pragma unroll
    for (int i = 0; i < 4; ++i)
#pragma unroll
        for (int j = 0; j < 4; ++j) acc[i][j] = 0.f;

    for (int k0 = 0; k0 < K; k0 += 16) {
        {   // A tile -> transposed
            int m = tid >> 2;
            int kk = (tid & 3) * 4;
            float4 v = *(const float4*)&A[(size_t)(bm + m) * K + k0 + kk];
            As[kk + 0][m] = v.x; As[kk + 1][m] = v.y;
            As[kk + 2][m] = v.z; As[kk + 3][m] = v.w;
        }
        {   // B tile -> direct
            int kk = tid >> 4;
            int n0 = (tid & 15) * 4;
            float4 v = *(const float4*)&Bm[(size_t)(k0 + kk) * N + bn + n0];
            *(float4*)&Bs[kk][n0] = v;
        }
        __syncthreads();
#pragma unroll
        for (int kk = 0; kk < 16; ++kk) {
            float4 a = *(const float4*)&As[kk][ty * 4];
            float4 b = *(const float4*)&Bs[kk][tx * 4];
            float av[4] = {a.x, a.y, a.z, a.w};
            float bv[4] = {b.x, b.y, b.z, b.w};
#pragma unroll
            for (int i = 0; i < 4; ++i)
#pragma unroll
                for (int j = 0; j < 4; ++j) acc[i][j] += av[i] * bv[j];
        }
        __syncthreads();
    }
#pragma unroll
    for (int i = 0; i < 4; ++i) {
        float4 v = make_float4(acc[i][0], acc[i][1], acc[i][2], acc[i][3]);
        *(float4*)&C[(size_t)(bm + ty * 4 + i) * N + bn + tx * 4] = v;
    }
}

// -------------------- bias value table: table[e] = dot(embs[e], scalar) ----
__global__ void bias_table_kernel(const float* __restrict__ embs,
                                  const float* __restrict__ scal,
                                  float* __restrict__ table) {
    int e = threadIdx.x >> 5;      // 8 warps, one per entry
    int lane = threadIdx.x & 31;
    float s = embs[e * DH_ + lane] * scal[lane]
            + embs[e * DH_ + 32 + lane] * scal[32 + lane];
#pragma unroll
    for (int off = 16; off; off >>= 1) s += __shfl_xor_sync(0xffffffffu, s, off);
    if (lane == 0) table[e] = s;
}

// -------------------- scatter-add into bias_mat ----------------------------
__global__ void scatter_bias_kernel(const int* __restrict__ ab,
                                    const float* __restrict__ table,
                                    float* __restrict__ bias_mat) {
    int e = blockIdx.x * blockDim.x + threadIdx.x;
    if (e < E_) {
        int et = ab[e * 4 + 0];
        int b  = ab[e * 4 + 1];
        int qi = ab[e * 4 + 2];
        int ki = ab[e * 4 + 3];
        atomicAdd(&bias_mat[((size_t)b * N_ + qi) * N_ + ki], table[et]);
    }
}

// -------------------- summed_keys[b,n,h] = sum_a k[b,n,h,a] ----------------
__global__ void sumk_kernel(const float* __restrict__ kmat,
                            float* __restrict__ sk) {
    int w = (blockIdx.x * blockDim.x + threadIdx.x) >> 5;  // one warp / element
    int lane = threadIdx.x & 31;
    const float* p = kmat + (size_t)w * DH_;
    float s = p[lane] + p[lane + 32];
#pragma unroll
    for (int off = 16; off; off >>= 1) s += __shfl_xor_sync(0xffffffffu, s, off);
    if (lane == 0) sk[w] = s;
}

// -------------------- fused causal attention (flash-style) -----------------
// grid (N/64, H, B), 256 threads, 4x4 per thread over a 64x64 tile.
// score = (q.k + bias_mat[b,q,k]*summed_keys[b,k,h]) * rsqrt(DH), causal.
#define SPAD 68
__global__ void attn_kernel(const float* __restrict__ q,
                            const float* __restrict__ kmat,
                            const float* __restrict__ vmat,
                            const float* __restrict__ bias_mat,
                            const float* __restrict__ sk,
                            float* __restrict__ ctx) {
    extern __shared__ float smem[];
    float (*Qs)[SPAD] = (float(*)[SPAD])smem;                 // [a][row]
    float (*Ks)[SPAD] = (float(*)[SPAD])(smem + 64 * SPAD);   // [a][col]
    float (*Vs)[SPAD] = (float(*)[SPAD])(smem + 2 * 64 * SPAD); // [k][c]
    float (*Ps)[SPAD] = (float(*)[SPAD])(smem + 3 * 64 * SPAD); // [row][k]

    const int qt = blockIdx.x, h = blockIdx.y, b = blockIdx.z;
    const int tid = threadIdx.x, tx = tid & 15, ty = tid >> 4;

    // load Q tile, transposed to [a][row]
    {
        int r = tid >> 2;
        int a0 = (tid & 3) * 16;
        const float* src = q + (((size_t)(b * N_ + qt * 64 + r)) * H_ + h) * DH_ + a0;
#pragma unroll
        for (int c4 = 0; c4 < 4; ++c4) {
            float4 v = *(const float4*)(src + c4 * 4);
            Qs[a0 + c4 * 4 + 0][r] = v.x;
            Qs[a0 + c4 * 4 + 1][r] = v.y;
            Qs[a0 + c4 * 4 + 2][r] = v.z;
            Qs[a0 + c4 * 4 + 3][r] = v.w;
        }
    }

    float m[4], l[4], o[4][4];
#pragma unroll
    for (int i = 0; i < 4; ++i) {
        m[i] = -3.0e38f; l[i] = 0.f;
#pragma unroll
        for (int j = 0; j < 4; ++j) o[i][j] = 0.f;
    }

    for (int kt = 0; kt <= qt; ++kt) {
        // load K (transposed) and V (direct) tiles
        {
            int r = tid >> 2;
            int a0 = (tid & 3) * 16;
            const float* ks = kmat + (((size_t)(b * N_ + kt * 64 + r)) * H_ + h) * DH_ + a0;
            const float* vs = vmat + (((size_t)(b * N_ + kt * 64 + r)) * H_ + h) * DH_ + a0;
#pragma unroll
            for (int c4 = 0; c4 < 4; ++c4) {
                float4 kv = *(const float4*)(ks + c4 * 4);
                Ks[a0 + c4 * 4 + 0][r] = kv.x;
                Ks[a0 + c4 * 4 + 1][r] = kv.y;
                Ks[a0 + c4 * 4 + 2][r] = kv.z;
                Ks[a0 + c4 * 4 + 3][r] = kv.w;
                float4 vv = *(const float4*)(vs + c4 * 4);
                *(float4*)&Vs[r][a0 + c4 * 4] = vv;
            }
        }
        __syncthreads();

        // S = Q.K^T (64x64, 4x4 per thread)
        float s[4][4];
#pragma unroll
        for (int i = 0; i < 4; ++i)
#pragma unroll
            for (int j = 0; j < 4; ++j) s[i][j] = 0.f;
#pragma unroll 8
        for (int a = 0; a < 64; ++a) {
            float4 qa = *(const float4*)&Qs[a][ty * 4];
            float4 kb = *(const float4*)&Ks[a][tx * 4];
            float av[4] = {qa.x, qa.y, qa.z, qa.w};
            float bv[4] = {kb.x, kb.y, kb.z, kb.w};
#pragma unroll
            for (int i = 0; i < 4; ++i)
#pragma unroll
                for (int j = 0; j < 4; ++j) s[i][j] += av[i] * bv[j];
        }

        // bias + scale + causal mask
        float skv[4];
#pragma unroll
        for (int j = 0; j < 4; ++j)
            skv[j] = sk[(size_t)(b * N_ + kt * 64 + tx * 4 + j) * H_ + h];
#pragma unroll
        for (int i = 0; i < 4; ++i) {
            int qg = qt * 64 + ty * 4 + i;
            const float* brow = bias_mat + ((size_t)b * N_ + qg) * N_ + kt * 64 + tx * 4;
#pragma unroll
            for (int j = 0; j < 4; ++j) {
                int kg = kt * 64 + tx * 4 + j;
                float val = (s[i][j] + brow[j] * skv[j]) * 0.125f;
                s[i][j] = (kg <= qg) ? val : -3.0e38f;
            }
        }

        // online softmax update + write P tile
#pragma unroll
        for (int i = 0; i < 4; ++i) {
            float mx = fmaxf(fmaxf(s[i][0], s[i][1]), fmaxf(s[i][2], s[i][3]));
#pragma unroll
            for (int off = 8; off; off >>= 1)
                mx = fmaxf(mx, __shfl_xor_sync(0xffffffffu, mx, off, 16));
            float mn = fmaxf(m[i], mx);
            float corr = __expf(m[i] - mn);
            float psum = 0.f;
#pragma unroll
            for (int j = 0; j < 4; ++j) {
                float p = __expf(s[i][j] - mn);
                s[i][j] = p;
                psum += p;
            }
#pragma unroll
            for (int off = 8; off; off >>= 1)
                psum += __shfl_xor_sync(0xffffffffu, psum, off, 16);
            l[i] = l[i] * corr + psum;
            m[i] = mn;
#pragma unroll
            for (int j = 0; j < 4; ++j) o[i][j] *= corr;
            int r = ty * 4 + i;
#pragma unroll
            for (int j = 0; j < 4; ++j) Ps[r][tx * 4 + j] = s[i][j];
        }
        __syncthreads();

        // O += P * V
#pragma unroll 8
        for (int kk = 0; kk < 64; ++kk) {
            float4 vv = *(const float4*)&Vs[kk][tx * 4];
            float pv[4];
#pragma unroll
            for (int i = 0; i < 4; ++i) pv[i] = Ps[ty * 4 + i][kk];
#pragma unroll
            for (int i = 0; i < 4; ++i) {
                o[i][0] += pv[i] * vv.x;
                o[i][1] += pv[i] * vv.y;
                o[i][2] += pv[i] * vv.z;
                o[i][3] += pv[i] * vv.w;
            }
        }
        __syncthreads();
    }

    // normalize + write context[b, q, h, :]
#pragma unroll
    for (int i = 0; i < 4; ++i) {
        float inv = 1.0f / l[i];
        int qg = qt * 64 + ty * 4 + i;
        float4 v = make_float4(o[i][0] * inv, o[i][1] * inv,
                               o[i][2] * inv, o[i][3] * inv);
        *(float4*)&ctx[(((size_t)(b * N_ + qg)) * H_ + h) * DH_ + tx * 4] = v;
    }
}

// -------------------- launch ------------------------------------------------
extern "C" void kernel_launch(void* const* d_in, const int* in_sizes, int n_in,
                              void* d_out, int out_size) {
    const float* states     = (const float*)d_in[0];
    const float* key_states = (const float*)d_in[1];
    // d_in[2] = masks (known causal tril; unused)
    const int*   ab         = (const int*)d_in[3];
    const float* Wq         = (const float*)d_in[4];
    const float* Wk         = (const float*)d_in[5];
    const float* Wv         = (const float*)d_in[6];
    const float* Wo         = (const float*)d_in[7];
    const float* bias_embs  = (const float*)d_in[8];
    const float* bias_scal  = (const float*)d_in[9];
    float* out = (float*)d_out;

    float *gq, *gk, *gv, *gctx, *gbias, *gsk, *gtable;
    cudaGetSymbolAddress((void**)&gq,     g_q);
    cudaGetSymbolAddress((void**)&gk,     g_k);
    cudaGetSymbolAddress((void**)&gv,     g_v);
    cudaGetSymbolAddress((void**)&gctx,   g_ctx);
    cudaGetSymbolAddress((void**)&gbias,  g_bias);
    cudaGetSymbolAddress((void**)&gsk,    g_sk);
    cudaGetSymbolAddress((void**)&gtable, g_table);

    const int smem_attn = 4 * 64 * SPAD * (int)sizeof(float);  // 69632 B
    cudaFuncSetAttribute(attn_kernel,
                         cudaFuncAttributeMaxDynamicSharedMemorySize, smem_attn);

    dim3 gblk(BN_ / 64, D_ / 64);   // (64, 8)
    gemm_kernel<<<gblk, 256>>>(states,     Wq, gq, BN_, D_, D_);
    gemm_kernel<<<gblk, 256>>>(key_states, Wk, gk, BN_, D_, D_);
    gemm_kernel<<<gblk, 256>>>(key_states, Wv, gv, BN_, D_, D_);

    bias_table_kernel<<<1, 256>>>(bias_embs, bias_scal, gtable);
    cudaMemsetAsync(gbias, 0, sizeof(float) * B_ * N_ * N_, 0);
    scatter_bias_kernel<<<(E_ + 255) / 256, 256>>>(ab, gtable, gbias);

    sumk_kernel<<<(B_ * N_ * H_ * 32) / 256, 256>>>(gk, gsk);

    dim3 agrid(N_ / 64, H_, B_);    // (8, 8, 8)
    attn_kernel<<<agrid, 256, smem_attn>>>(gq, gk, gv, gbias, gsk, gctx);

    gemm_kernel<<<gblk, 256>>>(gctx, Wo, out, BN_, D_, D_);
}

// round 4
// speedup vs baseline: 1.7409x; 1.7409x over previous
#include <cuda_runtime.h>
#include <cuda_bf16.h>
#include <cstdint>
#include <math.h>

// Problem constants
#define B_  8
#define N_  512
#define D_  512
#define H_  8
#define DH_ 64
#define E_  32768
#define BIASDIM_ 8
#define BN_ (B_ * N_)          // 4096 rows

// -------------------- scratch (device globals; no allocs allowed) ----------
__device__ float g_q[BN_ * D_];
__device__ float g_k[BN_ * D_];
__device__ float g_v[BN_ * D_];
__device__ float g_ctx[BN_ * D_];
__device__ float g_bias[B_ * N_ * N_];
__device__ float g_sk[B_ * N_ * H_];
__device__ float g_table[BIASDIM_];

// -------------------- helpers ----------------------------------------------
__device__ __forceinline__ float to_tf32(float x) {
    uint32_t u;
    asm("cvt.rna.tf32.f32 %0, %1;" : "=r"(u) : "f"(x));
    return __uint_as_float(u);
}

__device__ __forceinline__ void mma_tf32(float* d, const uint32_t* a, const uint32_t* b) {
    asm volatile(
        "mma.sync.aligned.m16n8k8.row.col.f32.tf32.tf32.f32 "
        "{%0,%1,%2,%3}, {%4,%5,%6,%7}, {%8,%9}, {%0,%1,%2,%3};\n"
        : "+f"(d[0]), "+f"(d[1]), "+f"(d[2]), "+f"(d[3])
        : "r"(a[0]), "r"(a[1]), "r"(a[2]), "r"(a[3]), "r"(b[0]), "r"(b[1]));
}

// -------------------- tf32 tensor-core GEMM --------------------------------
// C[M,N] = A[M,K] * B[K,N], row-major. Block tile 128x64, KB=32,
// 256 threads = 8 warps as 4(m) x 2(n), warp tile 32x32 (2 m16 x 4 n8).
__global__ __launch_bounds__(256) void gemm_tf32(const float* __restrict__ A,
                                                 const float* __restrict__ Bm,
                                                 float* __restrict__ C,
                                                 int M, int N, int K) {
    __shared__ float As[128][36];   // [m][k], pad: bank = 4r+c, conflict-free
    __shared__ float Bs[32][72];    // [k][n], 64 cols + 8 pad: bank = 8c+r

    const int tid  = threadIdx.x;
    const int lane = tid & 31;
    const int wid  = tid >> 5;
    const int wm   = (wid & 3) * 32;
    const int wn   = (wid >> 2) * 32;
    const int bm   = blockIdx.x * 128, bn = blockIdx.y * 64;
    const int r = lane >> 2, c = lane & 3;

    float acc[2][4][4];
#pragma unroll
    for (int mt = 0; mt < 2; ++mt)
#pragma unroll
        for (int nt = 0; nt < 4; ++nt)
#pragma unroll
            for (int i = 0; i < 4; ++i) acc[mt][nt][i] = 0.f;

    float4 pa[4], pb[2];

    // ---- initial global load (k0 = 0)
#pragma unroll
    for (int it = 0; it < 4; ++it) {
        int idx = tid + it * 256;           // A: 128 rows x 8 float4
        int m = idx >> 3, kq = idx & 7;
        pa[it] = *(const float4*)&A[(size_t)(bm + m) * K + kq * 4];
    }
#pragma unroll
    for (int it = 0; it < 2; ++it) {
        int idx = tid + it * 256;           // B: 32 k x 16 float4
        int n4 = idx & 15, kk = idx >> 4;
        pb[it] = *(const float4*)&Bm[(size_t)kk * N + bn + n4 * 4];
    }
    // store to smem (with tf32 rounding)
#pragma unroll
    for (int it = 0; it < 4; ++it) {
        int idx = tid + it * 256;
        int m = idx >> 3, kq = idx & 7;
        float4 v = pa[it];
        float4 w = make_float4(to_tf32(v.x), to_tf32(v.y), to_tf32(v.z), to_tf32(v.w));
        *(float4*)&As[m][kq * 4] = w;
    }
#pragma unroll
    for (int it = 0; it < 2; ++it) {
        int idx = tid + it * 256;
        int n4 = idx & 15, kk = idx >> 4;
        float4 v = pb[it];
        float4 w = make_float4(to_tf32(v.x), to_tf32(v.y), to_tf32(v.z), to_tf32(v.w));
        *(float4*)&Bs[kk][n4 * 4] = w;
    }
    __syncthreads();

    for (int k0 = 0; k0 < K; k0 += 32) {
        // prefetch next tile into registers
        if (k0 + 32 < K) {
#pragma unroll
            for (int it = 0; it < 4; ++it) {
                int idx = tid + it * 256;
                int m = idx >> 3, kq = idx & 7;
                pa[it] = *(const float4*)&A[(size_t)(bm + m) * K + k0 + 32 + kq * 4];
            }
#pragma unroll
            for (int it = 0; it < 2; ++it) {
                int idx = tid + it * 256;
                int n4 = idx & 15, kk = idx >> 4;
                pb[it] = *(const float4*)&Bm[(size_t)(k0 + 32 + kk) * N + bn + n4 * 4];
            }
        }

        // compute 4 k8 steps from smem
#pragma unroll
        for (int ks = 0; ks < 4; ++ks) {
            const int k8 = ks * 8;
            uint32_t afr[2][4], bfr[4][2];
#pragma unroll
            for (int mt = 0; mt < 2; ++mt) {
                int mrow = wm + mt * 16;
                afr[mt][0] = __float_as_uint(As[mrow + r][k8 + c]);
                afr[mt][1] = __float_as_uint(As[mrow + r + 8][k8 + c]);
                afr[mt][2] = __float_as_uint(As[mrow + r][k8 + c + 4]);
                afr[mt][3] = __float_as_uint(As[mrow + r + 8][k8 + c + 4]);
            }
#pragma unroll
            for (int nt = 0; nt < 4; ++nt) {
                int ncol = wn + nt * 8 + r;
                bfr[nt][0] = __float_as_uint(Bs[k8 + c][ncol]);
                bfr[nt][1] = __float_as_uint(Bs[k8 + c + 4][ncol]);
            }
#pragma unroll
            for (int mt = 0; mt < 2; ++mt)
#pragma unroll
                for (int nt = 0; nt < 4; ++nt)
                    mma_tf32(acc[mt][nt], afr[mt], bfr[nt]);
        }
        __syncthreads();

        if (k0 + 32 < K) {
#pragma unroll
            for (int it = 0; it < 4; ++it) {
                int idx = tid + it * 256;
                int m = idx >> 3, kq = idx & 7;
                float4 v = pa[it];
                float4 w = make_float4(to_tf32(v.x), to_tf32(v.y), to_tf32(v.z), to_tf32(v.w));
                *(float4*)&As[m][kq * 4] = w;
            }
#pragma unroll
            for (int it = 0; it < 2; ++it) {
                int idx = tid + it * 256;
                int n4 = idx & 15, kk = idx >> 4;
                float4 v = pb[it];
                float4 w = make_float4(to_tf32(v.x), to_tf32(v.y), to_tf32(v.z), to_tf32(v.w));
                *(float4*)&Bs[kk][n4 * 4] = w;
            }
            __syncthreads();
        }
    }

    // epilogue
#pragma unroll
    for (int mt = 0; mt < 2; ++mt) {
#pragma unroll
        for (int nt = 0; nt < 4; ++nt) {
            int row0 = bm + wm + mt * 16 + r;
            int col  = bn + wn + nt * 8 + c * 2;
            *(float2*)&C[(size_t)row0 * N + col] =
                make_float2(acc[mt][nt][0], acc[mt][nt][1]);
            *(float2*)&C[(size_t)(row0 + 8) * N + col] =
                make_float2(acc[mt][nt][2], acc[mt][nt][3]);
        }
    }
}

// -------------------- bias value table: table[e] = dot(embs[e], scalar) ----
__global__ void bias_table_kernel(const float* __restrict__ embs,
                                  const float* __restrict__ scal,
                                  float* __restrict__ table) {
    int e = threadIdx.x >> 5;      // 8 warps, one per entry
    int lane = threadIdx.x & 31;
    float s = embs[e * DH_ + lane] * scal[lane]
            + embs[e * DH_ + 32 + lane] * scal[32 + lane];
#pragma unroll
    for (int off = 16; off; off >>= 1) s += __shfl_xor_sync(0xffffffffu, s, off);
    if (lane == 0) table[e] = s;
}

// -------------------- scatter-add into bias_mat ----------------------------
__global__ void scatter_bias_kernel(const int* __restrict__ ab,
                                    const float* __restrict__ table,
                                    float* __restrict__ bias_mat) {
    int e = blockIdx.x * blockDim.x + threadIdx.x;
    if (e < E_) {
        int et = ab[e * 4 + 0];
        int b  = ab[e * 4 + 1];
        int qi = ab[e * 4 + 2];
        int ki = ab[e * 4 + 3];
        atomicAdd(&bias_mat[((size_t)b * N_ + qi) * N_ + ki], table[et]);
    }
}

// -------------------- summed_keys[b,n,h] = sum_a k[b,n,h,a] ----------------
__global__ void sumk_kernel(const float* __restrict__ kmat,
                            float* __restrict__ sk) {
    int w = (blockIdx.x * blockDim.x + threadIdx.x) >> 5;  // one warp / element
    int lane = threadIdx.x & 31;
    const float* p = kmat + (size_t)w * DH_;
    float s = p[lane] + p[lane + 32];
#pragma unroll
    for (int off = 16; off; off >>= 1) s += __shfl_xor_sync(0xffffffffu, s, off);
    if (lane == 0) sk[w] = s;
}

// -------------------- fused causal attention (flash-style) -----------------
// grid (N/64, H, B), 256 threads, 4x4 per thread over a 64x64 tile.
// score = (q.k + bias_mat[b,q,k]*summed_keys[b,k,h]) * rsqrt(DH), causal.
#define SPAD 68
__global__ void attn_kernel(const float* __restrict__ q,
                            const float* __restrict__ kmat,
                            const float* __restrict__ vmat,
                            const float* __restrict__ bias_mat,
                            const float* __restrict__ sk,
                            float* __restrict__ ctx) {
    extern __shared__ float smem[];
    float (*Qs)[SPAD] = (float(*)[SPAD])smem;                 // [a][row]
    float (*Ks)[SPAD] = (float(*)[SPAD])(smem + 64 * SPAD);   // [a][col]
    float (*Vs)[SPAD] = (float(*)[SPAD])(smem + 2 * 64 * SPAD); // [k][c]
    float (*Ps)[SPAD] = (float(*)[SPAD])(smem + 3 * 64 * SPAD); // [row][k]

    const int qt = blockIdx.x, h = blockIdx.y, b = blockIdx.z;
    const int tid = threadIdx.x, tx = tid & 15, ty = tid >> 4;

    // load Q tile, transposed to [a][row]
    {
        int r = tid >> 2;
        int a0 = (tid & 3) * 16;
        const float* src = q + (((size_t)(b * N_ + qt * 64 + r)) * H_ + h) * DH_ + a0;
#pragma unroll
        for (int c4 = 0; c4 < 4; ++c4) {
            float4 v = *(const float4*)(src + c4 * 4);
            Qs[a0 + c4 * 4 + 0][r] = v.x;
            Qs[a0 + c4 * 4 + 1][r] = v.y;
            Qs[a0 + c4 * 4 + 2][r] = v.z;
            Qs[a0 + c4 * 4 + 3][r] = v.w;
        }
    }

    float m[4], l[4], o[4][4];
#pragma unroll
    for (int i = 0; i < 4; ++i) {
        m[i] = -3.0e38f; l[i] = 0.f;
#pragma unroll
        for (int j = 0; j < 4; ++j) o[i][j] = 0.f;
    }

    for (int kt = 0; kt <= qt; ++kt) {
        // load K (transposed) and V (direct) tiles
        {
            int r = tid >> 2;
            int a0 = (tid & 3) * 16;
            const float* ks = kmat + (((size_t)(b * N_ + kt * 64 + r)) * H_ + h) * DH_ + a0;
            const float* vs = vmat + (((size_t)(b * N_ + kt * 64 + r)) * H_ + h) * DH_ + a0;
#pragma unroll
            for (int c4 = 0; c4 < 4; ++c4) {
                float4 kv = *(const float4*)(ks + c4 * 4);
                Ks[a0 + c4 * 4 + 0][r] = kv.x;
                Ks[a0 + c4 * 4 + 1][r] = kv.y;
                Ks[a0 + c4 * 4 + 2][r] = kv.z;
                Ks[a0 + c4 * 4 + 3][r] = kv.w;
                float4 vv = *(const float4*)(vs + c4 * 4);
                *(float4*)&Vs[r][a0 + c4 * 4] = vv;
            }
        }
        __syncthreads();

        // S = Q.K^T (64x64, 4x4 per thread)
        float s[4][4];
#pragma unroll
        for (int i = 0; i < 4; ++i)
#pragma unroll
            for (int j = 0; j < 4; ++j) s[i][j] = 0.f;
#pragma unroll 8
        for (int a = 0; a < 64; ++a) {
            float4 qa = *(const float4*)&Qs[a][ty * 4];
            float4 kb = *(const float4*)&Ks[a][tx * 4];
            float av[4] = {qa.x, qa.y, qa.z, qa.w};
            float bv[4] = {kb.x, kb.y, kb.z, kb.w};
#pragma unroll
            for (int i = 0; i < 4; ++i)
#pragma unroll
                for (int j = 0; j < 4; ++j) s[i][j] += av[i] * bv[j];
        }

        // bias + scale + causal mask
        float skv[4];
#pragma unroll
        for (int j = 0; j < 4; ++j)
            skv[j] = sk[(size_t)(b * N_ + kt * 64 + tx * 4 + j) * H_ + h];
#pragma unroll
        for (int i = 0; i < 4; ++i) {
            int qg = qt * 64 + ty * 4 + i;
            const float* brow = bias_mat + ((size_t)b * N_ + qg) * N_ + kt * 64 + tx * 4;
#pragma unroll
            for (int j = 0; j < 4; ++j) {
                int kg = kt * 64 + tx * 4 + j;
                float val = (s[i][j] + brow[j] * skv[j]) * 0.125f;
                s[i][j] = (kg <= qg) ? val : -3.0e38f;
            }
        }

        // online softmax update + write P tile
#pragma unroll
        for (int i = 0; i < 4; ++i) {
            float mx = fmaxf(fmaxf(s[i][0], s[i][1]), fmaxf(s[i][2], s[i][3]));
#pragma unroll
            for (int off = 8; off; off >>= 1)
                mx = fmaxf(mx, __shfl_xor_sync(0xffffffffu, mx, off, 16));
            float mn = fmaxf(m[i], mx);
            float corr = __expf(m[i] - mn);
            float psum = 0.f;
#pragma unroll
            for (int j = 0; j < 4; ++j) {
                float p = __expf(s[i][j] - mn);
                s[i][j] = p;
                psum += p;
            }
#pragma unroll
            for (int off = 8; off; off >>= 1)
                psum += __shfl_xor_sync(0xffffffffu, psum, off, 16);
            l[i] = l[i] * corr + psum;
            m[i] = mn;
#pragma unroll
            for (int j = 0; j < 4; ++j) o[i][j] *= corr;
            int r = ty * 4 + i;
#pragma unroll
            for (int j = 0; j < 4; ++j) Ps[r][tx * 4 + j] = s[i][j];
        }
        __syncthreads();

        // O += P * V
#pragma unroll 8
        for (int kk = 0; kk < 64; ++kk) {
            float4 vv = *(const float4*)&Vs[kk][tx * 4];
            float pv[4];
#pragma unroll
            for (int i = 0; i < 4; ++i) pv[i] = Ps[ty * 4 + i][kk];
#pragma unroll
            for (int i = 0; i < 4; ++i) {
                o[i][0] += pv[i] * vv.x;
                o[i][1] += pv[i] * vv.y;
                o[i][2] += pv[i] * vv.z;
                o[i][3] += pv[i] * vv.w;
            }
        }
        __syncthreads();
    }

    // normalize + write context[b, q, h, :]
#pragma unroll
    for (int i = 0; i < 4; ++i) {
        float inv = 1.0f / l[i];
        int qg = qt * 64 + ty * 4 + i;
        float4 v = make_float4(o[i][0] * inv, o[i][1] * inv,
                               o[i][2] * inv, o[i][3] * inv);
        *(float4*)&ctx[(((size_t)(b * N_ + qg)) * H_ + h) * DH_ + tx * 4] = v;
    }
}

// -------------------- launch ------------------------------------------------
extern "C" void kernel_launch(void* const* d_in, const int* in_sizes, int n_in,
                              void* d_out, int out_size) {
    const float* states     = (const float*)d_in[0];
    const float* key_states = (const float*)d_in[1];
    // d_in[2] = masks (known causal tril; unused)
    const int*   ab         = (const int*)d_in[3];
    const float* Wq         = (const float*)d_in[4];
    const float* Wk         = (const float*)d_in[5];
    const float* Wv         = (const float*)d_in[6];
    const float* Wo         = (const float*)d_in[7];
    const float* bias_embs  = (const float*)d_in[8];
    const float* bias_scal  = (const float*)d_in[9];
    float* out = (float*)d_out;

    float *gq, *gk, *gv, *gctx, *gbias, *gsk, *gtable;
    cudaGetSymbolAddress((void**)&gq,     g_q);
    cudaGetSymbolAddress((void**)&gk,     g_k);
    cudaGetSymbolAddress((void**)&gv,     g_v);
    cudaGetSymbolAddress((void**)&gctx,   g_ctx);
    cudaGetSymbolAddress((void**)&gbias,  g_bias);
    cudaGetSymbolAddress((void**)&gsk,    g_sk);
    cudaGetSymbolAddress((void**)&gtable, g_table);

    const int smem_attn = 4 * 64 * SPAD * (int)sizeof(float);  // 69632 B
    cudaFuncSetAttribute(attn_kernel,
                         cudaFuncAttributeMaxDynamicSharedMemorySize, smem_attn);

    dim3 gblk(BN_ / 128, D_ / 64);   // (32, 8)
    gemm_tf32<<<gblk, 256>>>(states,     Wq, gq, BN_, D_, D_);
    gemm_tf32<<<gblk, 256>>>(key_states, Wk, gk, BN_, D_, D_);
    gemm_tf32<<<gblk, 256>>>(key_states, Wv, gv, BN_, D_, D_);

    bias_table_kernel<<<1, 256>>>(bias_embs, bias_scal, gtable);
    cudaMemsetAsync(gbias, 0, sizeof(float) * B_ * N_ * N_, 0);
    scatter_bias_kernel<<<(E_ + 255) / 256, 256>>>(ab, gtable, gbias);

    sumk_kernel<<<(B_ * N_ * H_ * 32) / 256, 256>>>(gk, gsk);

    dim3 agrid(N_ / 64, H_, B_);    // (8, 8, 8)
    attn_kernel<<<agrid, 256, smem_attn>>>(gq, gk, gv, gbias, gsk, gctx);

    gemm_tf32<<<gblk, 256>>>(gctx, Wo, out, BN_, D_, D_);
}

// round 5
// speedup vs baseline: 1.7941x; 1.0305x over previous
#include <cuda_runtime.h>
#include <cuda_fp16.h>
#include <cuda_bf16.h>
#include <cstdint>
#include <math.h>

// Problem constants
#define B_  8
#define N_  512
#define D_  512
#define H_  8
#define DH_ 64
#define E_  32768
#define BIASDIM_ 8
#define BN_ (B_ * N_)          // 4096 rows

// -------------------- scratch (device globals; no allocs allowed) ----------
__device__ float g_q[BN_ * D_];
__device__ float g_k[BN_ * D_];
__device__ float g_v[BN_ * D_];
__device__ float g_ctx[BN_ * D_];
__device__ float g_bias[B_ * N_ * N_];
__device__ float g_sk[B_ * N_ * H_];
__device__ float g_table[BIASDIM_];

// -------------------- helpers ----------------------------------------------
__device__ __forceinline__ uint32_t pack_half2(float x, float y) {
    __half2 h = __floats2half2_rn(x, y);
    return *(uint32_t*)&h;
}

__device__ __forceinline__ void mma_f16(float* d, const uint32_t* a, const uint32_t* b) {
    asm volatile(
        "mma.sync.aligned.m16n8k16.row.col.f32.f16.f16.f32 "
        "{%0,%1,%2,%3}, {%4,%5,%6,%7}, {%8,%9}, {%0,%1,%2,%3};\n"
        : "+f"(d[0]), "+f"(d[1]), "+f"(d[2]), "+f"(d[3])
        : "r"(a[0]), "r"(a[1]), "r"(a[2]), "r"(a[3]), "r"(b[0]), "r"(b[1]));
}

// -------------------- fp16 tensor-core GEMM (device body) ------------------
// C[M,N] = A[M,K] * B[K,N], row-major fp32 in/out, fp16 mma, fp32 accum.
// Block tile 128x64, KB=32, 256 threads = 8 warps (4m x 2n), warp 32x32.
#define APITCH 40   // halfs; bank(A[m][2c]) = (20m + c) % 32, conflict-free
#define BPITCH 40
__device__ __forceinline__ void gemm_f16_body(const float* __restrict__ A,
                                              const float* __restrict__ Bm,
                                              float* __restrict__ C,
                                              int M, int N, int K,
                                              int bm, int bn) {
    __shared__ __half As[128][APITCH];   // [m][k]
    __shared__ __half Bs[64][BPITCH];    // [n][k]  (transposed)

    const int tid  = threadIdx.x;
    const int lane = tid & 31;
    const int wid  = tid >> 5;
    const int wm   = (wid & 3) * 32;
    const int wn   = (wid >> 2) * 32;
    const int r = lane >> 2, c = lane & 3;

    float acc[2][4][4];
#pragma unroll
    for (int mt = 0; mt < 2; ++mt)
#pragma unroll
        for (int nt = 0; nt < 4; ++nt)
#pragma unroll
            for (int i = 0; i < 4; ++i) acc[mt][nt][i] = 0.f;

    float4 pa[4], pb[2];

    // ---- initial global load (k0 = 0)
#pragma unroll
    for (int it = 0; it < 4; ++it) {
        int idx = tid + it * 256;           // A: 128 rows x 8 float4
        int m = idx >> 3, kq = idx & 7;
        pa[it] = *(const float4*)&A[(size_t)(bm + m) * K + kq * 4];
    }
#pragma unroll
    for (int it = 0; it < 2; ++it) {
        int idx = tid + it * 256;           // B: 32 k x 16 float4
        int n4 = idx & 15, kk = idx >> 4;
        pb[it] = *(const float4*)&Bm[(size_t)kk * N + bn + n4 * 4];
    }
    // store to smem (fp16)
#pragma unroll
    for (int it = 0; it < 4; ++it) {
        int idx = tid + it * 256;
        int m = idx >> 3, kq = idx & 7;
        float4 v = pa[it];
        uint2 w = make_uint2(pack_half2(v.x, v.y), pack_half2(v.z, v.w));
        *(uint2*)&As[m][kq * 4] = w;
    }
#pragma unroll
    for (int it = 0; it < 2; ++it) {
        int idx = tid + it * 256;
        int n4 = idx & 15, kk = idx >> 4;
        float4 v = pb[it];
        Bs[n4 * 4 + 0][kk] = __float2half_rn(v.x);
        Bs[n4 * 4 + 1][kk] = __float2half_rn(v.y);
        Bs[n4 * 4 + 2][kk] = __float2half_rn(v.z);
        Bs[n4 * 4 + 3][kk] = __float2half_rn(v.w);
    }
    __syncthreads();

    for (int k0 = 0; k0 < K; k0 += 32) {
        // prefetch next tile into registers
        if (k0 + 32 < K) {
#pragma unroll
            for (int it = 0; it < 4; ++it) {
                int idx = tid + it * 256;
                int m = idx >> 3, kq = idx & 7;
                pa[it] = *(const float4*)&A[(size_t)(bm + m) * K + k0 + 32 + kq * 4];
            }
#pragma unroll
            for (int it = 0; it < 2; ++it) {
                int idx = tid + it * 256;
                int n4 = idx & 15, kk = idx >> 4;
                pb[it] = *(const float4*)&Bm[(size_t)(k0 + 32 + kk) * N + bn + n4 * 4];
            }
        }

        // compute 2 k16 steps from smem
#pragma unroll
        for (int ks = 0; ks < 2; ++ks) {
            const int k16 = ks * 16;
            uint32_t afr[2][4], bfr[4][2];
#pragma unroll
            for (int mt = 0; mt < 2; ++mt) {
                int mrow = wm + mt * 16;
                afr[mt][0] = *(const uint32_t*)&As[mrow + r][k16 + 2 * c];
                afr[mt][1] = *(const uint32_t*)&As[mrow + r + 8][k16 + 2 * c];
                afr[mt][2] = *(const uint32_t*)&As[mrow + r][k16 + 2 * c + 8];
                afr[mt][3] = *(const uint32_t*)&As[mrow + r + 8][k16 + 2 * c + 8];
            }
#pragma unroll
            for (int nt = 0; nt < 4; ++nt) {
                int ncol = wn + nt * 8 + r;
                bfr[nt][0] = *(const uint32_t*)&Bs[ncol][k16 + 2 * c];
                bfr[nt][1] = *(const uint32_t*)&Bs[ncol][k16 + 2 * c + 8];
            }
#pragma unroll
            for (int mt = 0; mt < 2; ++mt)
#pragma unroll
                for (int nt = 0; nt < 4; ++nt)
                    mma_f16(acc[mt][nt], afr[mt], bfr[nt]);
        }
        __syncthreads();

        if (k0 + 32 < K) {
#pragma unroll
            for (int it = 0; it < 4; ++it) {
                int idx = tid + it * 256;
                int m = idx >> 3, kq = idx & 7;
                float4 v = pa[it];
                uint2 w = make_uint2(pack_half2(v.x, v.y), pack_half2(v.z, v.w));
                *(uint2*)&As[m][kq * 4] = w;
            }
#pragma unroll
            for (int it = 0; it < 2; ++it) {
                int idx = tid + it * 256;
                int n4 = idx & 15, kk = idx >> 4;
                float4 v = pb[it];
                Bs[n4 * 4 + 0][kk] = __float2half_rn(v.x);
                Bs[n4 * 4 + 1][kk] = __float2half_rn(v.y);
                Bs[n4 * 4 + 2][kk] = __float2half_rn(v.z);
                Bs[n4 * 4 + 3][kk] = __float2half_rn(v.w);
            }
            __syncthreads();
        }
    }

    // epilogue
#pragma unroll
    for (int mt = 0; mt < 2; ++mt) {
#pragma unroll
        for (int nt = 0; nt < 4; ++nt) {
            int row0 = bm + wm + mt * 16 + r;
            int col  = bn + wn + nt * 8 + c * 2;
            *(float2*)&C[(size_t)row0 * N + col] =
                make_float2(acc[mt][nt][0], acc[mt][nt][1]);
            *(float2*)&C[(size_t)(row0 + 8) * N + col] =
                make_float2(acc[mt][nt][2], acc[mt][nt][3]);
        }
    }
}

// fused Q/K/V projection: grid.z picks (A, B, C) triple
__global__ __launch_bounds__(256) void qkv_gemm_kernel(
        const float* __restrict__ states, const float* __restrict__ key_states,
        const float* __restrict__ Wq, const float* __restrict__ Wk,
        const float* __restrict__ Wv,
        float* __restrict__ q, float* __restrict__ k, float* __restrict__ v) {
    const float* A; const float* Bm; float* C;
    if (blockIdx.z == 0)      { A = states;     Bm = Wq; C = q; }
    else if (blockIdx.z == 1) { A = key_states; Bm = Wk; C = k; }
    else                      { A = key_states; Bm = Wv; C = v; }
    gemm_f16_body(A, Bm, C, BN_, D_, D_, blockIdx.x * 128, blockIdx.y * 64);
}

__global__ __launch_bounds__(256) void out_gemm_kernel(
        const float* __restrict__ A, const float* __restrict__ Bm,
        float* __restrict__ C) {
    gemm_f16_body(A, Bm, C, BN_, D_, D_, blockIdx.x * 128, blockIdx.y * 64);
}

// -------------------- bias value table: table[e] = dot(embs[e], scalar) ----
__global__ void bias_table_kernel(const float* __restrict__ embs,
                                  const float* __restrict__ scal,
                                  float* __restrict__ table) {
    int e = threadIdx.x >> 5;      // 8 warps, one per entry
    int lane = threadIdx.x & 31;
    float s = embs[e * DH_ + lane] * scal[lane]
            + embs[e * DH_ + 32 + lane] * scal[32 + lane];
#pragma unroll
    for (int off = 16; off; off >>= 1) s += __shfl_xor_sync(0xffffffffu, s, off);
    if (lane == 0) table[e] = s;
}

// -------------------- scatter-add into bias_mat ----------------------------
__global__ void scatter_bias_kernel(const int* __restrict__ ab,
                                    const float* __restrict__ table,
                                    float* __restrict__ bias_mat) {
    int e = blockIdx.x * blockDim.x + threadIdx.x;
    if (e < E_) {
        int et = ab[e * 4 + 0];
        int b  = ab[e * 4 + 1];
        int qi = ab[e * 4 + 2];
        int ki = ab[e * 4 + 3];
        atomicAdd(&bias_mat[((size_t)b * N_ + qi) * N_ + ki], table[et]);
    }
}

// -------------------- summed_keys[b,n,h] = sum_a k[b,n,h,a] ----------------
__global__ void sumk_kernel(const float* __restrict__ kmat,
                            float* __restrict__ sk) {
    int w = (blockIdx.x * blockDim.x + threadIdx.x) >> 5;  // one warp / element
    int lane = threadIdx.x & 31;
    const float* p = kmat + (size_t)w * DH_;
    float s = p[lane] + p[lane + 32];
#pragma unroll
    for (int off = 16; off; off >>= 1) s += __shfl_xor_sync(0xffffffffu, s, off);
    if (lane == 0) sk[w] = s;
}

// -------------------- fused causal attention (flash-style) -----------------
// grid (N/64, H, B), 256 threads, 4x4 per thread over a 64x64 tile.
// score = (q.k + bias_mat[b,q,k]*summed_keys[b,k,h]) * rsqrt(DH), causal.
#define SPAD 68
__global__ void attn_kernel(const float* __restrict__ q,
                            const float* __restrict__ kmat,
                            const float* __restrict__ vmat,
                            const float* __restrict__ bias_mat,
                            const float* __restrict__ sk,
                            float* __restrict__ ctx) {
    extern __shared__ float smem[];
    float (*Qs)[SPAD] = (float(*)[SPAD])smem;                 // [a][row]
    float (*Ks)[SPAD] = (float(*)[SPAD])(smem + 64 * SPAD);   // [a][col]
    float (*Vs)[SPAD] = (float(*)[SPAD])(smem + 2 * 64 * SPAD); // [k][c]
    float (*Ps)[SPAD] = (float(*)[SPAD])(smem + 3 * 64 * SPAD); // [row][k]

    const int qt = blockIdx.x, h = blockIdx.y, b = blockIdx.z;
    const int tid = threadIdx.x, tx = tid & 15, ty = tid >> 4;

    // load Q tile, transposed to [a][row]
    {
        int r = tid >> 2;
        int a0 = (tid & 3) * 16;
        const float* src = q + (((size_t)(b * N_ + qt * 64 + r)) * H_ + h) * DH_ + a0;
#pragma unroll
        for (int c4 = 0; c4 < 4; ++c4) {
            float4 v = *(const float4*)(src + c4 * 4);
            Qs[a0 + c4 * 4 + 0][r] = v.x;
            Qs[a0 + c4 * 4 + 1][r] = v.y;
            Qs[a0 + c4 * 4 + 2][r] = v.z;
            Qs[a0 + c4 * 4 + 3][r] = v.w;
        }
    }

    float m[4], l[4], o[4][4];
#pragma unroll
    for (int i = 0; i < 4; ++i) {
        m[i] = -3.0e38f; l[i] = 0.f;
#pragma unroll
        for (int j = 0; j < 4; ++j) o[i][j] = 0.f;
    }

    for (int kt = 0; kt <= qt; ++kt) {
        // load K (transposed) and V (direct) tiles
        {
            int r = tid >> 2;
            int a0 = (tid & 3) * 16;
            const float* ks = kmat + (((size_t)(b * N_ + kt * 64 + r)) * H_ + h) * DH_ + a0;
            const float* vs = vmat + (((size_t)(b * N_ + kt * 64 + r)) * H_ + h) * DH_ + a0;
#pragma unroll
            for (int c4 = 0; c4 < 4; ++c4) {
                float4 kv = *(const float4*)(ks + c4 * 4);
                Ks[a0 + c4 * 4 + 0][r] = kv.x;
                Ks[a0 + c4 * 4 + 1][r] = kv.y;
                Ks[a0 + c4 * 4 + 2][r] = kv.z;
                Ks[a0 + c4 * 4 + 3][r] = kv.w;
                float4 vv = *(const float4*)(vs + c4 * 4);
                *(float4*)&Vs[r][a0 + c4 * 4] = vv;
            }
        }
        __syncthreads();

        // S = Q.K^T (64x64, 4x4 per thread)
        float s[4][4];
#pragma unroll
        for (int i = 0; i < 4; ++i)
#pragma unroll
            for (int j = 0; j < 4; ++j) s[i][j] = 0.f;
#pragma unroll 8
        for (int a = 0; a < 64; ++a) {
            float4 qa = *(const float4*)&Qs[a][ty * 4];
            float4 kb = *(const float4*)&Ks[a][tx * 4];
            float av[4] = {qa.x, qa.y, qa.z, qa.w};
            float bv[4] = {kb.x, kb.y, kb.z, kb.w};
#pragma unroll
            for (int i = 0; i < 4; ++i)
#pragma unroll
                for (int j = 0; j < 4; ++j) s[i][j] += av[i] * bv[j];
        }

        // bias + scale + causal mask
        float skv[4];
#pragma unroll
        for (int j = 0; j < 4; ++j)
            skv[j] = sk[(size_t)(b * N_ + kt * 64 + tx * 4 + j) * H_ + h];
#pragma unroll
        for (int i = 0; i < 4; ++i) {
            int qg = qt * 64 + ty * 4 + i;
            const float* brow = bias_mat + ((size_t)b * N_ + qg) * N_ + kt * 64 + tx * 4;
#pragma unroll
            for (int j = 0; j < 4; ++j) {
                int kg = kt * 64 + tx * 4 + j;
                float val = (s[i][j] + brow[j] * skv[j]) * 0.125f;
                s[i][j] = (kg <= qg) ? val : -3.0e38f;
            }
        }

        // online softmax update + write P tile
#pragma unroll
        for (int i = 0; i < 4; ++i) {
            float mx = fmaxf(fmaxf(s[i][0], s[i][1]), fmaxf(s[i][2], s[i][3]));
#pragma unroll
            for (int off = 8; off; off >>= 1)
                mx = fmaxf(mx, __shfl_xor_sync(0xffffffffu, mx, off, 16));
            float mn = fmaxf(m[i], mx);
            float corr = __expf(m[i] - mn);
            float psum = 0.f;
#pragma unroll
            for (int j = 0; j < 4; ++j) {
                float p = __expf(s[i][j] - mn);
                s[i][j] = p;
                psum += p;
            }
#pragma unroll
            for (int off = 8; off; off >>= 1)
                psum += __shfl_xor_sync(0xffffffffu, psum, off, 16);
            l[i] = l[i] * corr + psum;
            m[i] = mn;
#pragma unroll
            for (int j = 0; j < 4; ++j) o[i][j] *= corr;
            int r = ty * 4 + i;
#pragma unroll
            for (int j = 0; j < 4; ++j) Ps[r][tx * 4 + j] = s[i][j];
        }
        __syncthreads();

        // O += P * V
#pragma unroll 8
        for (int kk = 0; kk < 64; ++kk) {
            float4 vv = *(const float4*)&Vs[kk][tx * 4];
            float pv[4];
#pragma unroll
            for (int i = 0; i < 4; ++i) pv[i] = Ps[ty * 4 + i][kk];
#pragma unroll
            for (int i = 0; i < 4; ++i) {
                o[i][0] += pv[i] * vv.x;
                o[i][1] += pv[i] * vv.y;
                o[i][2] += pv[i] * vv.z;
                o[i][3] += pv[i] * vv.w;
            }
        }
        __syncthreads();
    }

    // normalize + write context[b, q, h, :]
#pragma unroll
    for (int i = 0; i < 4; ++i) {
        float inv = 1.0f / l[i];
        int qg = qt * 64 + ty * 4 + i;
        float4 v = make_float4(o[i][0] * inv, o[i][1] * inv,
                               o[i][2] * inv, o[i][3] * inv);
        *(float4*)&ctx[(((size_t)(b * N_ + qg)) * H_ + h) * DH_ + tx * 4] = v;
    }
}

// -------------------- launch ------------------------------------------------
extern "C" void kernel_launch(void* const* d_in, const int* in_sizes, int n_in,
                              void* d_out, int out_size) {
    const float* states     = (const float*)d_in[0];
    const float* key_states = (const float*)d_in[1];
    // d_in[2] = masks (known causal tril; unused)
    const int*   ab         = (const int*)d_in[3];
    const float* Wq         = (const float*)d_in[4];
    const float* Wk         = (const float*)d_in[5];
    const float* Wv         = (const float*)d_in[6];
    const float* Wo         = (const float*)d_in[7];
    const float* bias_embs  = (const float*)d_in[8];
    const float* bias_scal  = (const float*)d_in[9];
    float* out = (float*)d_out;

    float *gq, *gk, *gv, *gctx, *gbias, *gsk, *gtable;
    cudaGetSymbolAddress((void**)&gq,     g_q);
    cudaGetSymbolAddress((void**)&gk,     g_k);
    cudaGetSymbolAddress((void**)&gv,     g_v);
    cudaGetSymbolAddress((void**)&gctx,   g_ctx);
    cudaGetSymbolAddress((void**)&gbias,  g_bias);
    cudaGetSymbolAddress((void**)&gsk,    g_sk);
    cudaGetSymbolAddress((void**)&gtable, g_table);

    const int smem_attn = 4 * 64 * SPAD * (int)sizeof(float);  // 69632 B
    cudaFuncSetAttribute(attn_kernel,
                         cudaFuncAttributeMaxDynamicSharedMemorySize, smem_attn);

    // fused QKV projection (3 GEMMs in one launch)
    dim3 qkvgrid(BN_ / 128, D_ / 64, 3);   // (32, 8, 3)
    qkv_gemm_kernel<<<qkvgrid, 256>>>(states, key_states, Wq, Wk, Wv, gq, gk, gv);

    bias_table_kernel<<<1, 256>>>(bias_embs, bias_scal, gtable);
    cudaMemsetAsync(gbias, 0, sizeof(float) * B_ * N_ * N_, 0);
    scatter_bias_kernel<<<(E_ + 255) / 256, 256>>>(ab, gtable, gbias);

    sumk_kernel<<<(B_ * N_ * H_ * 32) / 256, 256>>>(gk, gsk);

    dim3 agrid(N_ / 64, H_, B_);    // (8, 8, 8)
    attn_kernel<<<agrid, 256, smem_attn>>>(gq, gk, gv, gbias, gsk, gctx);

    dim3 ogrid(BN_ / 128, D_ / 64);  // (32, 8)
    out_gemm_kernel<<<ogrid, 256>>>(gctx, Wo, out);
}

// round 8
// speedup vs baseline: 3.0224x; 1.6847x over previous
#include <cuda_runtime.h>
#include <cuda_fp16.h>
#include <cstdint>
#include <math.h>

#define B_  8
#define N_  512
#define D_  512
#define H_  8
#define DH_ 64
#define E_  32768
#define BN_ (B_ * N_)          // 4096 rows

// -------------------- scratch (device globals) -----------------------------
__device__ __half g_qh[BN_ * D_];
__device__ __half g_kh[BN_ * D_];
__device__ __half g_vh[BN_ * D_];
__device__ float  g_ctx[BN_ * D_];
__device__ float  g_bias[B_ * N_ * N_];
__device__ float  g_sk[B_ * N_ * H_];
__device__ float  g_table[8];

// -------------------- helpers ----------------------------------------------
__device__ __forceinline__ uint32_t smem_u32(const void* p) {
    uint32_t a;
    asm("{ .reg .u64 t; cvta.to.shared.u64 t, %1; cvt.u32.u64 %0, t; }"
        : "=r"(a) : "l"(p));
    return a;
}
__device__ __forceinline__ uint32_t pack_half2(float x, float y) {
    __half2 h = __floats2half2_rn(x, y);
    return *(uint32_t*)&h;
}
__device__ __forceinline__ void mma_f16(float* d, const uint32_t* a, const uint32_t* b) {
    asm volatile(
        "mma.sync.aligned.m16n8k16.row.col.f32.f16.f16.f32 "
        "{%0,%1,%2,%3}, {%4,%5,%6,%7}, {%8,%9}, {%0,%1,%2,%3};\n"
        : "+f"(d[0]), "+f"(d[1]), "+f"(d[2]), "+f"(d[3])
        : "r"(a[0]), "r"(a[1]), "r"(a[2]), "r"(a[3]), "r"(b[0]), "r"(b[1]));
}
__device__ __forceinline__ void ldsm_x4(uint32_t& r0, uint32_t& r1,
                                        uint32_t& r2, uint32_t& r3, uint32_t a) {
    asm volatile("ldmatrix.sync.aligned.m8n8.x4.shared.b16 {%0,%1,%2,%3}, [%4];"
                 : "=r"(r0), "=r"(r1), "=r"(r2), "=r"(r3) : "r"(a));
}
__device__ __forceinline__ void ldsm_x2(uint32_t& r0, uint32_t& r1, uint32_t a) {
    asm volatile("ldmatrix.sync.aligned.m8n8.x2.shared.b16 {%0,%1}, [%2];"
                 : "=r"(r0), "=r"(r1) : "r"(a));
}
__device__ __forceinline__ void ldsm_x4t(uint32_t& r0, uint32_t& r1,
                                         uint32_t& r2, uint32_t& r3, uint32_t a) {
    asm volatile("ldmatrix.sync.aligned.m8n8.x4.trans.shared.b16 {%0,%1,%2,%3}, [%4];"
                 : "=r"(r0), "=r"(r1), "=r"(r2), "=r"(r3) : "r"(a));
}

// -------------------- fp16 tensor-core GEMM body ---------------------------
// C[M,N] = A[M,K](f32) * B[K,N](f32), fp16 mma, fp32 accum.
// Block tile 128x64, KB=32, 256 threads = 8 warps (4m x 2n), warp 32x32.
#define APITCH 40
#define BPITCH 40
template <bool HALF_OUT>
__device__ __forceinline__ void gemm_f16_body(const float* __restrict__ A,
                                              const float* __restrict__ Bm,
                                              void* __restrict__ Cv,
                                              int M, int N, int K,
                                              int bm, int bn) {
    __shared__ __half As[128][APITCH];   // [m][k]
    __shared__ __half Bs[64][BPITCH];    // [n][k] (transposed)

    const int tid  = threadIdx.x;
    const int lane = tid & 31;
    const int wid  = tid >> 5;
    const int wm   = (wid & 3) * 32;
    const int wn   = (wid >> 2) * 32;
    const int r = lane >> 2, c = lane & 3;

    float acc[2][4][4];
#pragma unroll
    for (int mt = 0; mt < 2; ++mt)
#pragma unroll
        for (int nt = 0; nt < 4; ++nt)
#pragma unroll
            for (int i = 0; i < 4; ++i) acc[mt][nt][i] = 0.f;

    float4 pa[4], pb[2];

#pragma unroll
    for (int it = 0; it < 4; ++it) {
        int idx = tid + it * 256;
        int m = idx >> 3, kq = idx & 7;
        pa[it] = *(const float4*)&A[(size_t)(bm + m) * K + kq * 4];
    }
#pragma unroll
    for (int it = 0; it < 2; ++it) {
        int idx = tid + it * 256;
        int n4 = idx & 15, kk = idx >> 4;
        pb[it] = *(const float4*)&Bm[(size_t)kk * N + bn + n4 * 4];
    }
#pragma unroll
    for (int it = 0; it < 4; ++it) {
        int idx = tid + it * 256;
        int m = idx >> 3, kq = idx & 7;
        float4 v = pa[it];
        uint2 w = make_uint2(pack_half2(v.x, v.y), pack_half2(v.z, v.w));
        *(uint2*)&As[m][kq * 4] = w;
    }
#pragma unroll
    for (int it = 0; it < 2; ++it) {
        int idx = tid + it * 256;
        int n4 = idx & 15, kk = idx >> 4;
        float4 v = pb[it];
        Bs[n4 * 4 + 0][kk] = __float2half_rn(v.x);
        Bs[n4 * 4 + 1][kk] = __float2half_rn(v.y);
        Bs[n4 * 4 + 2][kk] = __float2half_rn(v.z);
        Bs[n4 * 4 + 3][kk] = __float2half_rn(v.w);
    }
    __syncthreads();

    for (int k0 = 0; k0 < K; k0 += 32) {
        if (k0 + 32 < K) {
#pragma unroll
            for (int it = 0; it < 4; ++it) {
                int idx = tid + it * 256;
                int m = idx >> 3, kq = idx & 7;
                pa[it] = *(const float4*)&A[(size_t)(bm + m) * K + k0 + 32 + kq * 4];
            }
#pragma unroll
            for (int it = 0; it < 2; ++it) {
                int idx = tid + it * 256;
                int n4 = idx & 15, kk = idx >> 4;
                pb[it] = *(const float4*)&Bm[(size_t)(k0 + 32 + kk) * N + bn + n4 * 4];
            }
        }

#pragma unroll
        for (int ks = 0; ks < 2; ++ks) {
            const int k16 = ks * 16;
            uint32_t afr[2][4], bfr[4][2];
#pragma unroll
            for (int mt = 0; mt < 2; ++mt) {
                int mrow = wm + mt * 16;
                afr[mt][0] = *(const uint32_t*)&As[mrow + r][k16 + 2 * c];
                afr[mt][1] = *(const uint32_t*)&As[mrow + r + 8][k16 + 2 * c];
                afr[mt][2] = *(const uint32_t*)&As[mrow + r][k16 + 2 * c + 8];
                afr[mt][3] = *(const uint32_t*)&As[mrow + r + 8][k16 + 2 * c + 8];
            }
#pragma unroll
            for (int nt = 0; nt < 4; ++nt) {
                int ncol = wn + nt * 8 + r;
                bfr[nt][0] = *(const uint32_t*)&Bs[ncol][k16 + 2 * c];
                bfr[nt][1] = *(const uint32_t*)&Bs[ncol][k16 + 2 * c + 8];
            }
#pragma unroll
            for (int mt = 0; mt < 2; ++mt)
#pragma unroll
                for (int nt = 0; nt < 4; ++nt)
                    mma_f16(acc[mt][nt], afr[mt], bfr[nt]);
        }
        __syncthreads();

        if (k0 + 32 < K) {
#pragma unroll
            for (int it = 0; it < 4; ++it) {
                int idx = tid + it * 256;
                int m = idx >> 3, kq = idx & 7;
                float4 v = pa[it];
                uint2 w = make_uint2(pack_half2(v.x, v.y), pack_half2(v.z, v.w));
                *(uint2*)&As[m][kq * 4] = w;
            }
#pragma unroll
            for (int it = 0; it < 2; ++it) {
                int idx = tid + it * 256;
                int n4 = idx & 15, kk = idx >> 4;
                float4 v = pb[it];
                Bs[n4 * 4 + 0][kk] = __float2half_rn(v.x);
                Bs[n4 * 4 + 1][kk] = __float2half_rn(v.y);
                Bs[n4 * 4 + 2][kk] = __float2half_rn(v.z);
                Bs[n4 * 4 + 3][kk] = __float2half_rn(v.w);
            }
            __syncthreads();
        }
    }

#pragma unroll
    for (int mt = 0; mt < 2; ++mt) {
#pragma unroll
        for (int nt = 0; nt < 4; ++nt) {
            int row0 = bm + wm + mt * 16 + r;
            int col  = bn + wn + nt * 8 + c * 2;
            if (HALF_OUT) {
                __half* C = (__half*)Cv;
                *(__half2*)&C[(size_t)row0 * N + col] =
                    __floats2half2_rn(acc[mt][nt][0], acc[mt][nt][1]);
                *(__half2*)&C[(size_t)(row0 + 8) * N + col] =
                    __floats2half2_rn(acc[mt][nt][2], acc[mt][nt][3]);
            } else {
                float* C = (float*)Cv;
                *(float2*)&C[(size_t)row0 * N + col] =
                    make_float2(acc[mt][nt][0], acc[mt][nt][1]);
                *(float2*)&C[(size_t)(row0 + 8) * N + col] =
                    make_float2(acc[mt][nt][2], acc[mt][nt][3]);
            }
        }
    }
}

__global__ __launch_bounds__(256) void qkv_gemm_kernel(
        const float* __restrict__ states, const float* __restrict__ key_states,
        const float* __restrict__ Wq, const float* __restrict__ Wk,
        const float* __restrict__ Wv) {
    const float* A; const float* Bm; __half* C;
    if (blockIdx.z == 0)      { A = states;     Bm = Wq; C = g_qh; }
    else if (blockIdx.z == 1) { A = key_states; Bm = Wk; C = g_kh; }
    else                      { A = key_states; Bm = Wv; C = g_vh; }
    gemm_f16_body<true>(A, Bm, C, BN_, D_, D_, blockIdx.x * 128, blockIdx.y * 64);
}

__global__ __launch_bounds__(256) void out_gemm_kernel(
        const float* __restrict__ Wo, float* __restrict__ out) {
    gemm_f16_body<false>(g_ctx, Wo, out, BN_, D_, D_, blockIdx.x * 128, blockIdx.y * 64);
}

// -------------------- bias table --------------------------------------------
__global__ void bias_table_kernel(const float* __restrict__ embs,
                                  const float* __restrict__ scal,
                                  float* __restrict__ table) {
    int e = threadIdx.x >> 5;
    int lane = threadIdx.x & 31;
    float s = embs[e * DH_ + lane] * scal[lane]
            + embs[e * DH_ + 32 + lane] * scal[32 + lane];
#pragma unroll
    for (int off = 16; off; off >>= 1) s += __shfl_xor_sync(0xffffffffu, s, off);
    if (lane == 0) table[e] = s;
}

// -------------------- scatter-add into bias_mat -----------------------------
__global__ void scatter_bias_kernel(const int* __restrict__ ab,
                                    const float* __restrict__ table,
                                    float* __restrict__ bias_mat) {
    int e = blockIdx.x * blockDim.x + threadIdx.x;
    if (e < E_) {
        int et = ab[e * 4 + 0];
        int b  = ab[e * 4 + 1];
        int qi = ab[e * 4 + 2];
        int ki = ab[e * 4 + 3];
        atomicAdd(&bias_mat[((size_t)b * N_ + qi) * N_ + ki], table[et]);
    }
}

// -------------------- summed_keys (fp16 input) ------------------------------
__global__ void sumk_kernel(const __half* __restrict__ kmat,
                            float* __restrict__ sk) {
    int w = (blockIdx.x * blockDim.x + threadIdx.x) >> 5;
    int lane = threadIdx.x & 31;
    const __half* p = kmat + (size_t)w * DH_;
    float s = __half2float(p[lane]) + __half2float(p[lane + 32]);
#pragma unroll
    for (int off = 16; off; off >>= 1) s += __shfl_xor_sync(0xffffffffu, s, off);
    if (lane == 0) sk[w] = s;
}

// -------------------- fused causal attention: mma.sync + ldmatrix -----------
// grid (N/64, H, B), 128 threads = 4 warps; warp w owns q rows [16w, 16w+16).
#define QP 72
__global__ __launch_bounds__(128) void attn_kernel(
        const float* __restrict__ bias_mat, const float* __restrict__ sk,
        float* __restrict__ ctx) {
    __shared__ __half Qs[64][QP];
    __shared__ __half Ks[64][QP];
    __shared__ __half Vs[64][QP];
    __shared__ float  bsk[64];

    const int qt = blockIdx.x, h = blockIdx.y, b = blockIdx.z;
    const int tid = threadIdx.x, lane = tid & 31, warp = tid >> 5;
    const int r4 = lane >> 2, t4 = lane & 3;

    // stage Q tile (64 q rows x 64 dh)
#pragma unroll
    for (int it = 0; it < 4; ++it) {
        int idx = tid + it * 128;
        int row = idx >> 3, seg = idx & 7;
        *(uint4*)&Qs[row][seg * 8] =
            *(const uint4*)&g_qh[(size_t)(b * N_ + qt * 64 + row) * D_ + h * DH_ + seg * 8];
    }
    __syncthreads();

    // Q fragments (kept in registers for the whole block)
    uint32_t qf[4][4];
    {
        int lrow = lane & 15, lcol = (lane >> 4) * 8;
#pragma unroll
        for (int ks = 0; ks < 4; ++ks)
            ldsm_x4(qf[ks][0], qf[ks][1], qf[ks][2], qf[ks][3],
                    smem_u32(&Qs[warp * 16 + lrow][ks * 16 + lcol]));
    }

    float m1 = -3.0e38f, m2 = -3.0e38f, l1 = 0.f, l2 = 0.f;
    float o[8][4];
#pragma unroll
    for (int dt = 0; dt < 8; ++dt)
#pragma unroll
        for (int i = 0; i < 4; ++i) o[dt][i] = 0.f;

    const int qg1 = qt * 64 + warp * 16 + r4;
    const int qg2 = qg1 + 8;
    const float* bp1 = bias_mat + (size_t)(b * N_ + qg1) * N_;
    const float* bp2 = bias_mat + (size_t)(b * N_ + qg2) * N_;

    for (int kt = 0; kt <= qt; ++kt) {
        if (kt) __syncthreads();
        // stage K and V tiles
#pragma unroll
        for (int it = 0; it < 4; ++it) {
            int idx = tid + it * 128;
            int row = idx >> 3, seg = idx & 7;
            size_t g = (size_t)(b * N_ + kt * 64 + row) * D_ + h * DH_ + seg * 8;
            *(uint4*)&Ks[row][seg * 8] = *(const uint4*)&g_kh[g];
            *(uint4*)&Vs[row][seg * 8] = *(const uint4*)&g_vh[g];
        }
        if (tid < 64) bsk[tid] = sk[(size_t)(b * N_ + kt * 64 + tid) * H_ + h];
        __syncthreads();

        // S = Q K^T  (per warp: 16 x 64)
        float s[8][4];
#pragma unroll
        for (int nt = 0; nt < 8; ++nt) {
#pragma unroll
            for (int i = 0; i < 4; ++i) s[nt][i] = 0.f;
#pragma unroll
            for (int ks = 0; ks < 4; ++ks) {
                uint32_t bf[2];
                ldsm_x2(bf[0], bf[1],
                        smem_u32(&Ks[nt * 8 + (lane & 7)][ks * 16 + ((lane >> 3) & 1) * 8]));
                mma_f16(s[nt], qf[ks], bf);
            }
        }

        // bias + scale + causal mask; tile max
        float tm1 = -3.0e38f, tm2 = -3.0e38f;
#pragma unroll
        for (int nt = 0; nt < 8; ++nt) {
            int kl = nt * 8 + 2 * t4;
            int kg = kt * 64 + kl;
            float2 bv1 = *(const float2*)&bp1[kg];
            float2 bv2 = *(const float2*)&bp2[kg];
            float s0 = bsk[kl], s1 = bsk[kl + 1];
            s[nt][0] = (kg     <= qg1) ? (s[nt][0] + bv1.x * s0) * 0.125f : -3.0e38f;
            s[nt][1] = (kg + 1 <= qg1) ? (s[nt][1] + bv1.y * s1) * 0.125f : -3.0e38f;
            s[nt][2] = (kg     <= qg2) ? (s[nt][2] + bv2.x * s0) * 0.125f : -3.0e38f;
            s[nt][3] = (kg + 1 <= qg2) ? (s[nt][3] + bv2.y * s1) * 0.125f : -3.0e38f;
            tm1 = fmaxf(tm1, fmaxf(s[nt][0], s[nt][1]));
            tm2 = fmaxf(tm2, fmaxf(s[nt][2], s[nt][3]));
        }
        tm1 = fmaxf(tm1, __shfl_xor_sync(0xffffffffu, tm1, 1));
        tm1 = fmaxf(tm1, __shfl_xor_sync(0xffffffffu, tm1, 2));
        tm2 = fmaxf(tm2, __shfl_xor_sync(0xffffffffu, tm2, 1));
        tm2 = fmaxf(tm2, __shfl_xor_sync(0xffffffffu, tm2, 2));

        float mn1 = fmaxf(m1, tm1), mn2 = fmaxf(m2, tm2);
        float c1 = __expf(m1 - mn1), c2 = __expf(m2 - mn2);
        float sum1 = 0.f, sum2 = 0.f;
#pragma unroll
        for (int nt = 0; nt < 8; ++nt) {
            s[nt][0] = __expf(s[nt][0] - mn1);
            s[nt][1] = __expf(s[nt][1] - mn1);
            s[nt][2] = __expf(s[nt][2] - mn2);
            s[nt][3] = __expf(s[nt][3] - mn2);
            sum1 += s[nt][0] + s[nt][1];
            sum2 += s[nt][2] + s[nt][3];
        }
        sum1 += __shfl_xor_sync(0xffffffffu, sum1, 1);
        sum1 += __shfl_xor_sync(0xffffffffu, sum1, 2);
        sum2 += __shfl_xor_sync(0xffffffffu, sum2, 1);
        sum2 += __shfl_xor_sync(0xffffffffu, sum2, 2);
        l1 = l1 * c1 + sum1; m1 = mn1;
        l2 = l2 * c2 + sum2; m2 = mn2;
#pragma unroll
        for (int dt = 0; dt < 8; ++dt) {
            o[dt][0] *= c1; o[dt][1] *= c1;
            o[dt][2] *= c2; o[dt][3] *= c2;
        }

        // P fragments (fp16) directly from S accumulators
        uint32_t pf[4][4];
#pragma unroll
        for (int kst = 0; kst < 4; ++kst) {
            pf[kst][0] = pack_half2(s[2 * kst][0],     s[2 * kst][1]);
            pf[kst][1] = pack_half2(s[2 * kst][2],     s[2 * kst][3]);
            pf[kst][2] = pack_half2(s[2 * kst + 1][0], s[2 * kst + 1][1]);
            pf[kst][3] = pack_half2(s[2 * kst + 1][2], s[2 * kst + 1][3]);
        }

        // O += P V
#pragma unroll
        for (int g = 0; g < 4; ++g) {
#pragma unroll
            for (int kst = 0; kst < 4; ++kst) {
                uint32_t b0, b1, b2, b3;
                ldsm_x4t(b0, b1, b2, b3,
                         smem_u32(&Vs[kst * 16 + (lane & 15)][g * 16 + (lane >> 4) * 8]));
                uint32_t bfa[2] = {b0, b1}, bfb[2] = {b2, b3};
                mma_f16(o[2 * g],     pf[kst], bfa);
                mma_f16(o[2 * g + 1], pf[kst], bfb);
            }
        }
    }

    // normalize + write context fp32
    float inv1 = 1.0f / l1, inv2 = 1.0f / l2;
#pragma unroll
    for (int dt = 0; dt < 8; ++dt) {
        int col = h * DH_ + dt * 8 + 2 * t4;
        *(float2*)&ctx[(size_t)(b * N_ + qg1) * D_ + col] =
            make_float2(o[dt][0] * inv1, o[dt][1] * inv1);
        *(float2*)&ctx[(size_t)(b * N_ + qg2) * D_ + col] =
            make_float2(o[dt][2] * inv2, o[dt][3] * inv2);
    }
}

// -------------------- launch -------------------------------------------------
extern "C" void kernel_launch(void* const* d_in, const int* in_sizes, int n_in,
                              void* d_out, int out_size) {
    const float* states     = (const float*)d_in[0];
    const float* key_states = (const float*)d_in[1];
    const int*   ab         = (const int*)d_in[3];
    const float* Wq         = (const float*)d_in[4];
    const float* Wk         = (const float*)d_in[5];
    const float* Wv         = (const float*)d_in[6];
    const float* Wo         = (const float*)d_in[7];
    const float* bias_embs  = (const float*)d_in[8];
    const float* bias_scal  = (const float*)d_in[9];
    float* out = (float*)d_out;

    float *gbias, *gsk, *gtable, *gctx;
    __half* gkh;
    cudaGetSymbolAddress((void**)&gbias,  g_bias);
    cudaGetSymbolAddress((void**)&gsk,    g_sk);
    cudaGetSymbolAddress((void**)&gtable, g_table);
    cudaGetSymbolAddress((void**)&gctx,   g_ctx);
    cudaGetSymbolAddress((void**)&gkh,    g_kh);

    // QKV projections (fp16 out)
    dim3 qkvgrid(BN_ / 128, D_ / 64, 3);
    qkv_gemm_kernel<<<qkvgrid, 256>>>(states, key_states, Wq, Wk, Wv);

    bias_table_kernel<<<1, 256>>>(bias_embs, bias_scal, gtable);
    cudaMemsetAsync(gbias, 0, sizeof(float) * B_ * N_ * N_, 0);
    scatter_bias_kernel<<<(E_ + 255) / 256, 256>>>(ab, gtable, gbias);

    sumk_kernel<<<(B_ * N_ * H_ * 32) / 256, 256>>>(gkh, gsk);

    dim3 agrid(N_ / 64, H_, B_);
    attn_kernel<<<agrid, 128>>>(gbias, gsk, gctx);

    dim3 ogrid(BN_ / 128, D_ / 64);
    out_gemm_kernel<<<ogrid, 256>>>(Wo, out);
}

// round 9
// speedup vs baseline: 3.9860x; 1.3188x over previous
#include <cuda_runtime.h>
#include <cuda_fp16.h>
#include <cstdint>
#include <math.h>

#define B_  8
#define N_  512
#define D_  512
#define H_  8
#define DH_ 64
#define E_  32768
#define BN_ (B_ * N_)          // 4096 rows

// -------------------- scratch (device globals) -----------------------------
__device__ __half g_qh[BN_ * D_];
__device__ __half g_kh[BN_ * D_];
__device__ __half g_vh[BN_ * D_];
__device__ float  g_ctx[BN_ * D_];
__device__ float  g_bias[B_ * N_ * N_];
__device__ float  g_sk[B_ * N_ * H_];
__device__ __half g_wqt[D_ * D_];   // W^T fp16, [n][k]
__device__ __half g_wkt[D_ * D_];
__device__ __half g_wvt[D_ * D_];
__device__ __half g_wot[D_ * D_];

// -------------------- helpers ----------------------------------------------
__device__ __forceinline__ uint32_t smem_u32(const void* p) {
    uint32_t a;
    asm("{ .reg .u64 t; cvta.to.shared.u64 t, %1; cvt.u32.u64 %0, t; }"
        : "=r"(a) : "l"(p));
    return a;
}
__device__ __forceinline__ uint32_t pack_half2(float x, float y) {
    __half2 h = __floats2half2_rn(x, y);
    return *(uint32_t*)&h;
}
__device__ __forceinline__ void mma_f16(float* d, const uint32_t* a, const uint32_t* b) {
    asm volatile(
        "mma.sync.aligned.m16n8k16.row.col.f32.f16.f16.f32 "
        "{%0,%1,%2,%3}, {%4,%5,%6,%7}, {%8,%9}, {%0,%1,%2,%3};\n"
        : "+f"(d[0]), "+f"(d[1]), "+f"(d[2]), "+f"(d[3])
        : "r"(a[0]), "r"(a[1]), "r"(a[2]), "r"(a[3]), "r"(b[0]), "r"(b[1]));
}
__device__ __forceinline__ void ldsm_x4(uint32_t& r0, uint32_t& r1,
                                        uint32_t& r2, uint32_t& r3, uint32_t a) {
    asm volatile("ldmatrix.sync.aligned.m8n8.x4.shared.b16 {%0,%1,%2,%3}, [%4];"
                 : "=r"(r0), "=r"(r1), "=r"(r2), "=r"(r3) : "r"(a));
}
__device__ __forceinline__ void ldsm_x2(uint32_t& r0, uint32_t& r1, uint32_t a) {
    asm volatile("ldmatrix.sync.aligned.m8n8.x2.shared.b16 {%0,%1}, [%2];"
                 : "=r"(r0), "=r"(r1) : "r"(a));
}
__device__ __forceinline__ void ldsm_x4t(uint32_t& r0, uint32_t& r1,
                                         uint32_t& r2, uint32_t& r3, uint32_t a) {
    asm volatile("ldmatrix.sync.aligned.m8n8.x4.trans.shared.b16 {%0,%1,%2,%3}, [%4];"
                 : "=r"(r0), "=r"(r1), "=r"(r2), "=r"(r3) : "r"(a));
}

// -------------------- fp16 tensor-core GEMM (double-buffered) ---------------
// C[4096,512] = A[4096,512](f32) * Bt^T, Bt fp16 [n][k]. M,N,K fixed (512 K).
// Block 128x128, KB=32, 256 threads = 8 warps (2m x 4n), warp 64x32.
#define GP 40
template <bool HALF_OUT>
__device__ __forceinline__ void gemm_body(const float* __restrict__ A,
                                          const __half* __restrict__ Bt,
                                          void* __restrict__ Cv,
                                          int bm, int bn) {
    __shared__ __half As[2][128][GP];   // [m][k]
    __shared__ __half Bs[2][128][GP];   // [n][k]

    const int tid  = threadIdx.x;
    const int lane = tid & 31;
    const int wid  = tid >> 5;
    const int wm   = (wid & 1) * 64;
    const int wn   = (wid >> 1) * 32;

    float acc[4][4][4];
#pragma unroll
    for (int mt = 0; mt < 4; ++mt)
#pragma unroll
        for (int nt = 0; nt < 4; ++nt)
#pragma unroll
            for (int i = 0; i < 4; ++i) acc[mt][nt][i] = 0.f;

    const int am = tid >> 3, akq = tid & 7;       // A: rows am, am+32.. ; k quad
    const int bn_r = tid >> 2, bseg = tid & 3;    // B: row, 8-half segment

    float4 pa[4];
    uint4  pb[2];
#pragma unroll
    for (int it = 0; it < 4; ++it)
        pa[it] = *(const float4*)&A[(size_t)(bm + am + it * 32) * 512 + akq * 4];
#pragma unroll
    for (int it = 0; it < 2; ++it)
        pb[it] = *(const uint4*)&Bt[(size_t)(bn + bn_r + it * 64) * 512 + bseg * 8];
#pragma unroll
    for (int it = 0; it < 4; ++it) {
        float4 v = pa[it];
        *(uint2*)&As[0][am + it * 32][akq * 4] =
            make_uint2(pack_half2(v.x, v.y), pack_half2(v.z, v.w));
    }
#pragma unroll
    for (int it = 0; it < 2; ++it)
        *(uint4*)&Bs[0][bn_r + it * 64][bseg * 8] = pb[it];
    __syncthreads();

#pragma unroll 2
    for (int ch = 0; ch < 16; ++ch) {
        const int cur = ch & 1, nxt = cur ^ 1;
        if (ch < 15) {
            const int k0 = (ch + 1) * 32;
#pragma unroll
            for (int it = 0; it < 4; ++it)
                pa[it] = *(const float4*)&A[(size_t)(bm + am + it * 32) * 512 + k0 + akq * 4];
#pragma unroll
            for (int it = 0; it < 2; ++it)
                pb[it] = *(const uint4*)&Bt[(size_t)(bn + bn_r + it * 64) * 512 + k0 + bseg * 8];
        }

#pragma unroll
        for (int ks = 0; ks < 2; ++ks) {
            const int k16 = ks * 16;
            uint32_t afr[4][4], bfr[4][2];
#pragma unroll
            for (int mt = 0; mt < 4; ++mt)
                ldsm_x4(afr[mt][0], afr[mt][1], afr[mt][2], afr[mt][3],
                        smem_u32(&As[cur][wm + mt * 16 + (lane & 15)][k16 + (lane >> 4) * 8]));
#pragma unroll
            for (int nt = 0; nt < 4; ++nt)
                ldsm_x2(bfr[nt][0], bfr[nt][1],
                        smem_u32(&Bs[cur][wn + nt * 8 + (lane & 7)][k16 + ((lane >> 3) & 1) * 8]));
#pragma unroll
            for (int mt = 0; mt < 4; ++mt)
#pragma unroll
                for (int nt = 0; nt < 4; ++nt)
                    mma_f16(acc[mt][nt], afr[mt], bfr[nt]);
        }

        if (ch < 15) {
#pragma unroll
            for (int it = 0; it < 4; ++it) {
                float4 v = pa[it];
                *(uint2*)&As[nxt][am + it * 32][akq * 4] =
                    make_uint2(pack_half2(v.x, v.y), pack_half2(v.z, v.w));
            }
#pragma unroll
            for (int it = 0; it < 2; ++it)
                *(uint4*)&Bs[nxt][bn_r + it * 64][bseg * 8] = pb[it];
        }
        __syncthreads();
    }

    const int r = lane >> 2, c = lane & 3;
#pragma unroll
    for (int mt = 0; mt < 4; ++mt) {
#pragma unroll
        for (int nt = 0; nt < 4; ++nt) {
            int row0 = bm + wm + mt * 16 + r;
            int col  = bn + wn + nt * 8 + 2 * c;
            if (HALF_OUT) {
                __half* C = (__half*)Cv;
                *(__half2*)&C[(size_t)row0 * 512 + col] =
                    __floats2half2_rn(acc[mt][nt][0], acc[mt][nt][1]);
                *(__half2*)&C[(size_t)(row0 + 8) * 512 + col] =
                    __floats2half2_rn(acc[mt][nt][2], acc[mt][nt][3]);
            } else {
                float* C = (float*)Cv;
                *(float2*)&C[(size_t)row0 * 512 + col] =
                    make_float2(acc[mt][nt][0], acc[mt][nt][1]);
                *(float2*)&C[(size_t)(row0 + 8) * 512 + col] =
                    make_float2(acc[mt][nt][2], acc[mt][nt][3]);
            }
        }
    }
}

__global__ __launch_bounds__(256) void qkv_gemm_kernel(
        const float* __restrict__ states, const float* __restrict__ key_states) {
    const float* A; const __half* Bt; __half* C;
    if (blockIdx.z == 0)      { A = states;     Bt = g_wqt; C = g_qh; }
    else if (blockIdx.z == 1) { A = key_states; Bt = g_wkt; C = g_kh; }
    else                      { A = key_states; Bt = g_wvt; C = g_vh; }
    gemm_body<true>(A, Bt, C, blockIdx.x * 128, blockIdx.y * 128);
}

__global__ __launch_bounds__(256) void out_gemm_kernel(float* __restrict__ out) {
    gemm_body<false>(g_ctx, g_wot, out, blockIdx.x * 128, blockIdx.y * 128);
}

// -------------------- prep: transpose + convert weights ---------------------
__global__ void transpose_cvt_kernel(const float* __restrict__ wq,
                                     const float* __restrict__ wk,
                                     const float* __restrict__ wv,
                                     const float* __restrict__ wo) {
    const float* in; __half* out;
    switch (blockIdx.z) {
        case 0:  in = wq; out = g_wqt; break;
        case 1:  in = wk; out = g_wkt; break;
        case 2:  in = wv; out = g_wvt; break;
        default: in = wo; out = g_wot; break;
    }
    __shared__ float t[32][33];
    int tx = threadIdx.x, ty = threadIdx.y;
    int bx = blockIdx.x * 32, by = blockIdx.y * 32;
#pragma unroll
    for (int i = 0; i < 4; ++i)
        t[ty + 8 * i][tx] = in[(size_t)(by + ty + 8 * i) * D_ + bx + tx];
    __syncthreads();
#pragma unroll
    for (int i = 0; i < 4; ++i)
        out[(size_t)(bx + ty + 8 * i) * D_ + by + tx] =
            __float2half_rn(t[tx][ty + 8 * i]);
}

// -------------------- fused bias table + scatter-add ------------------------
__global__ void scatter_bias_kernel(const int* __restrict__ ab,
                                    const float* __restrict__ embs,
                                    const float* __restrict__ scal,
                                    float* __restrict__ bias_mat) {
    __shared__ float table[8];
    int tid = threadIdx.x;
    int e = tid >> 5, lane = tid & 31;
    {   // 8 warps compute the 8 table entries
        float s = embs[e * DH_ + lane] * scal[lane]
                + embs[e * DH_ + 32 + lane] * scal[32 + lane];
#pragma unroll
        for (int off = 16; off; off >>= 1) s += __shfl_xor_sync(0xffffffffu, s, off);
        if (lane == 0) table[e] = s;
    }
    __syncthreads();
    int i = blockIdx.x * 256 + tid;
    if (i < E_) {
        int et = ab[i * 4 + 0];
        int b  = ab[i * 4 + 1];
        int qi = ab[i * 4 + 2];
        int ki = ab[i * 4 + 3];
        atomicAdd(&bias_mat[((size_t)b * N_ + qi) * N_ + ki], table[et]);
    }
}

// -------------------- summed_keys: one thread per (b,n,h) -------------------
__global__ void sumk_kernel(const __half* __restrict__ kmat,
                            float* __restrict__ sk) {
    int t = blockIdx.x * 256 + threadIdx.x;     // 32768 threads
    const __half2* p = (const __half2*)(kmat + (size_t)(t >> 3) * 512 + (t & 7) * 64);
    float s = 0.f;
#pragma unroll
    for (int i = 0; i < 32; ++i) {
        float2 f = __half22float2(p[i]);
        s += f.x + f.y;
    }
    sk[t] = s;
}

// -------------------- fused causal attention: mma.sync + ldmatrix -----------
// grid (N/64, H, B), 128 threads = 4 warps; warp w owns q rows [16w, 16w+16).
#define QP 72
__global__ __launch_bounds__(128) void attn_kernel(
        const float* __restrict__ bias_mat, const float* __restrict__ sk,
        float* __restrict__ ctx) {
    __shared__ __half Qs[64][QP];
    __shared__ __half Ks[64][QP];
    __shared__ __half Vs[64][QP];
    __shared__ float  bsk[64];

    const int qt = blockIdx.x, h = blockIdx.y, b = blockIdx.z;
    const int tid = threadIdx.x, lane = tid & 31, warp = tid >> 5;
    const int r4 = lane >> 2, t4 = lane & 3;

#pragma unroll
    for (int it = 0; it < 4; ++it) {
        int idx = tid + it * 128;
        int row = idx >> 3, seg = idx & 7;
        *(uint4*)&Qs[row][seg * 8] =
            *(const uint4*)&g_qh[(size_t)(b * N_ + qt * 64 + row) * D_ + h * DH_ + seg * 8];
    }
    __syncthreads();

    uint32_t qf[4][4];
    {
        int lrow = lane & 15, lcol = (lane >> 4) * 8;
#pragma unroll
        for (int ks = 0; ks < 4; ++ks)
            ldsm_x4(qf[ks][0], qf[ks][1], qf[ks][2], qf[ks][3],
                    smem_u32(&Qs[warp * 16 + lrow][ks * 16 + lcol]));
    }

    float m1 = -3.0e38f, m2 = -3.0e38f, l1 = 0.f, l2 = 0.f;
    float o[8][4];
#pragma unroll
    for (int dt = 0; dt < 8; ++dt)
#pragma unroll
        for (int i = 0; i < 4; ++i) o[dt][i] = 0.f;

    const int qg1 = qt * 64 + warp * 16 + r4;
    const int qg2 = qg1 + 8;
    const float* bp1 = bias_mat + (size_t)(b * N_ + qg1) * N_;
    const float* bp2 = bias_mat + (size_t)(b * N_ + qg2) * N_;

    for (int kt = 0; kt <= qt; ++kt) {
        if (kt) __syncthreads();
#pragma unroll
        for (int it = 0; it < 4; ++it) {
            int idx = tid + it * 128;
            int row = idx >> 3, seg = idx & 7;
            size_t g = (size_t)(b * N_ + kt * 64 + row) * D_ + h * DH_ + seg * 8;
            *(uint4*)&Ks[row][seg * 8] = *(const uint4*)&g_kh[g];
            *(uint4*)&Vs[row][seg * 8] = *(const uint4*)&g_vh[g];
        }
        if (tid < 64) bsk[tid] = sk[(size_t)(b * N_ + kt * 64 + tid) * H_ + h];
        __syncthreads();

        float s[8][4];
#pragma unroll
        for (int nt = 0; nt < 8; ++nt) {
#pragma unroll
            for (int i = 0; i < 4; ++i) s[nt][i] = 0.f;
#pragma unroll
            for (int ks = 0; ks < 4; ++ks) {
                uint32_t bf[2];
                ldsm_x2(bf[0], bf[1],
                        smem_u32(&Ks[nt * 8 + (lane & 7)][ks * 16 + ((lane >> 3) & 1) * 8]));
                mma_f16(s[nt], qf[ks], bf);
            }
        }

        float tm1 = -3.0e38f, tm2 = -3.0e38f;
#pragma unroll
        for (int nt = 0; nt < 8; ++nt) {
            int kl = nt * 8 + 2 * t4;
            int kg = kt * 64 + kl;
            float2 bv1 = *(const float2*)&bp1[kg];
            float2 bv2 = *(const float2*)&bp2[kg];
            float s0 = bsk[kl], s1 = bsk[kl + 1];
            s[nt][0] = (kg     <= qg1) ? (s[nt][0] + bv1.x * s0) * 0.125f : -3.0e38f;
            s[nt][1] = (kg + 1 <= qg1) ? (s[nt][1] + bv1.y * s1) * 0.125f : -3.0e38f;
            s[nt][2] = (kg     <= qg2) ? (s[nt][2] + bv2.x * s0) * 0.125f : -3.0e38f;
            s[nt][3] = (kg + 1 <= qg2) ? (s[nt][3] + bv2.y * s1) * 0.125f : -3.0e38f;
            tm1 = fmaxf(tm1, fmaxf(s[nt][0], s[nt][1]));
            tm2 = fmaxf(tm2, fmaxf(s[nt][2], s[nt][3]));
        }
        tm1 = fmaxf(tm1, __shfl_xor_sync(0xffffffffu, tm1, 1));
        tm1 = fmaxf(tm1, __shfl_xor_sync(0xffffffffu, tm1, 2));
        tm2 = fmaxf(tm2, __shfl_xor_sync(0xffffffffu, tm2, 1));
        tm2 = fmaxf(tm2, __shfl_xor_sync(0xffffffffu, tm2, 2));

        float mn1 = fmaxf(m1, tm1), mn2 = fmaxf(m2, tm2);
        float c1 = __expf(m1 - mn1), c2 = __expf(m2 - mn2);
        float sum1 = 0.f, sum2 = 0.f;
#pragma unroll
        for (int nt = 0; nt < 8; ++nt) {
            s[nt][0] = __expf(s[nt][0] - mn1);
            s[nt][1] = __expf(s[nt][1] - mn1);
            s[nt][2] = __expf(s[nt][2] - mn2);
            s[nt][3] = __expf(s[nt][3] - mn2);
            sum1 += s[nt][0] + s[nt][1];
            sum2 += s[nt][2] + s[nt][3];
        }
        sum1 += __shfl_xor_sync(0xffffffffu, sum1, 1);
        sum1 += __shfl_xor_sync(0xffffffffu, sum1, 2);
        sum2 += __shfl_xor_sync(0xffffffffu, sum2, 1);
        sum2 += __shfl_xor_sync(0xffffffffu, sum2, 2);
        l1 = l1 * c1 + sum1; m1 = mn1;
        l2 = l2 * c2 + sum2; m2 = mn2;
#pragma unroll
        for (int dt = 0; dt < 8; ++dt) {
            o[dt][0] *= c1; o[dt][1] *= c1;
            o[dt][2] *= c2; o[dt][3] *= c2;
        }

        uint32_t pf[4][4];
#pragma unroll
        for (int kst = 0; kst < 4; ++kst) {
            pf[kst][0] = pack_half2(s[2 * kst][0],     s[2 * kst][1]);
            pf[kst][1] = pack_half2(s[2 * kst][2],     s[2 * kst][3]);
            pf[kst][2] = pack_half2(s[2 * kst + 1][0], s[2 * kst + 1][1]);
            pf[kst][3] = pack_half2(s[2 * kst + 1][2], s[2 * kst + 1][3]);
        }

#pragma unroll
        for (int g = 0; g < 4; ++g) {
#pragma unroll
            for (int kst = 0; kst < 4; ++kst) {
                uint32_t b0, b1, b2, b3;
                ldsm_x4t(b0, b1, b2, b3,
                         smem_u32(&Vs[kst * 16 + (lane & 15)][g * 16 + (lane >> 4) * 8]));
                uint32_t bfa[2] = {b0, b1}, bfb[2] = {b2, b3};
                mma_f16(o[2 * g],     pf[kst], bfa);
                mma_f16(o[2 * g + 1], pf[kst], bfb);
            }
        }
    }

    float inv1 = 1.0f / l1, inv2 = 1.0f / l2;
#pragma unroll
    for (int dt = 0; dt < 8; ++dt) {
        int col = h * DH_ + dt * 8 + 2 * t4;
        *(float2*)&ctx[(size_t)(b * N_ + qg1) * D_ + col] =
            make_float2(o[dt][0] * inv1, o[dt][1] * inv1);
        *(float2*)&ctx[(size_t)(b * N_ + qg2) * D_ + col] =
            make_float2(o[dt][2] * inv2, o[dt][3] * inv2);
    }
}

// -------------------- launch -------------------------------------------------
extern "C" void kernel_launch(void* const* d_in, const int* in_sizes, int n_in,
                              void* d_out, int out_size) {
    const float* states     = (const float*)d_in[0];
    const float* key_states = (const float*)d_in[1];
    const int*   ab         = (const int*)d_in[3];
    const float* Wq         = (const float*)d_in[4];
    const float* Wk         = (const float*)d_in[5];
    const float* Wv         = (const float*)d_in[6];
    const float* Wo         = (const float*)d_in[7];
    const float* bias_embs  = (const float*)d_in[8];
    const float* bias_scal  = (const float*)d_in[9];
    float* out = (float*)d_out;

    float *gbias, *gsk, *gctx;
    __half* gkh;
    cudaGetSymbolAddress((void**)&gbias, g_bias);
    cudaGetSymbolAddress((void**)&gsk,   g_sk);
    cudaGetSymbolAddress((void**)&gctx,  g_ctx);
    cudaGetSymbolAddress((void**)&gkh,   g_kh);

    // weight transpose + fp16 convert (once per call, ~3 us)
    dim3 tg(D_ / 32, D_ / 32, 4);
    transpose_cvt_kernel<<<tg, dim3(32, 8)>>>(Wq, Wk, Wv, Wo);

    // QKV projections
    dim3 qkvgrid(BN_ / 128, D_ / 128, 3);   // (32, 4, 3)
    qkv_gemm_kernel<<<qkvgrid, 256>>>(states, key_states);

    cudaMemsetAsync(gbias, 0, sizeof(float) * B_ * N_ * N_, 0);
    scatter_bias_kernel<<<(E_ + 255) / 256, 256>>>(ab, bias_embs, bias_scal, gbias);

    sumk_kernel<<<BN_ * H_ / 256, 256>>>(gkh, gsk);

    dim3 agrid(N_ / 64, H_, B_);
    attn_kernel<<<agrid, 128>>>(gbias, gsk, gctx);

    dim3 ogrid(BN_ / 128, D_ / 128);        // (32, 4)
    out_gemm_kernel<<<ogrid, 256>>>(out);
}

// round 10
// speedup vs baseline: 4.0929x; 1.0268x over previous
#include <cuda_runtime.h>
#include <cuda_fp16.h>
#include <cstdint>
#include <math.h>

#define B_  8
#define N_  512
#define D_  512
#define H_  8
#define DH_ 64
#define E_  32768
#define BN_ (B_ * N_)          // 4096 rows

// -------------------- scratch (device globals) -----------------------------
__device__ __half g_qh[BN_ * D_];
__device__ __half g_kh[BN_ * D_];
__device__ __half g_vh[BN_ * D_];
__device__ float  g_ctx[BN_ * D_];
__device__ float  g_bias[B_ * N_ * N_];
__device__ __half g_wqt[D_ * D_];   // W^T fp16, [n][k]
__device__ __half g_wkt[D_ * D_];
__device__ __half g_wvt[D_ * D_];
__device__ __half g_wot[D_ * D_];

// -------------------- helpers ----------------------------------------------
__device__ __forceinline__ uint32_t smem_u32(const void* p) {
    uint32_t a;
    asm("{ .reg .u64 t; cvta.to.shared.u64 t, %1; cvt.u32.u64 %0, t; }"
        : "=r"(a) : "l"(p));
    return a;
}
__device__ __forceinline__ uint32_t pack_half2(float x, float y) {
    __half2 h = __floats2half2_rn(x, y);
    return *(uint32_t*)&h;
}
__device__ __forceinline__ void mma_f16(float* d, const uint32_t* a, const uint32_t* b) {
    asm volatile(
        "mma.sync.aligned.m16n8k16.row.col.f32.f16.f16.f32 "
        "{%0,%1,%2,%3}, {%4,%5,%6,%7}, {%8,%9}, {%0,%1,%2,%3};\n"
        : "+f"(d[0]), "+f"(d[1]), "+f"(d[2]), "+f"(d[3])
        : "r"(a[0]), "r"(a[1]), "r"(a[2]), "r"(a[3]), "r"(b[0]), "r"(b[1]));
}
__device__ __forceinline__ void ldsm_x4(uint32_t& r0, uint32_t& r1,
                                        uint32_t& r2, uint32_t& r3, uint32_t a) {
    asm volatile("ldmatrix.sync.aligned.m8n8.x4.shared.b16 {%0,%1,%2,%3}, [%4];"
                 : "=r"(r0), "=r"(r1), "=r"(r2), "=r"(r3) : "r"(a));
}
__device__ __forceinline__ void ldsm_x2(uint32_t& r0, uint32_t& r1, uint32_t a) {
    asm volatile("ldmatrix.sync.aligned.m8n8.x2.shared.b16 {%0,%1}, [%2];"
                 : "=r"(r0), "=r"(r1) : "r"(a));
}
__device__ __forceinline__ void ldsm_x4t(uint32_t& r0, uint32_t& r1,
                                         uint32_t& r2, uint32_t& r3, uint32_t a) {
    asm volatile("ldmatrix.sync.aligned.m8n8.x4.trans.shared.b16 {%0,%1,%2,%3}, [%4];"
                 : "=r"(r0), "=r"(r1), "=r"(r2), "=r"(r3) : "r"(a));
}

// -------------------- fp16 tensor-core GEMM (double-buffered) ---------------
// C[4096,512] = A[4096,512](f32) * Bt^T, Bt fp16 [n][k]. K fixed 512.
// Block 128x128, KB=32, 256 threads = 8 warps (2m x 4n), warp 64x32.
#define GP 40
template <bool HALF_OUT>
__device__ __forceinline__ void gemm_body(const float* __restrict__ A,
                                          const __half* __restrict__ Bt,
                                          void* __restrict__ Cv,
                                          int bm, int bn) {
    __shared__ __half As[2][128][GP];   // [m][k]
    __shared__ __half Bs[2][128][GP];   // [n][k]

    const int tid  = threadIdx.x;
    const int lane = tid & 31;
    const int wid  = tid >> 5;
    const int wm   = (wid & 1) * 64;
    const int wn   = (wid >> 1) * 32;

    float acc[4][4][4];
#pragma unroll
    for (int mt = 0; mt < 4; ++mt)
#pragma unroll
        for (int nt = 0; nt < 4; ++nt)
#pragma unroll
            for (int i = 0; i < 4; ++i) acc[mt][nt][i] = 0.f;

    const int am = tid >> 3, akq = tid & 7;
    const int bn_r = tid >> 2, bseg = tid & 3;

    float4 pa[4];
    uint4  pb[2];
#pragma unroll
    for (int it = 0; it < 4; ++it)
        pa[it] = *(const float4*)&A[(size_t)(bm + am + it * 32) * 512 + akq * 4];
#pragma unroll
    for (int it = 0; it < 2; ++it)
        pb[it] = *(const uint4*)&Bt[(size_t)(bn + bn_r + it * 64) * 512 + bseg * 8];
#pragma unroll
    for (int it = 0; it < 4; ++it) {
        float4 v = pa[it];
        *(uint2*)&As[0][am + it * 32][akq * 4] =
            make_uint2(pack_half2(v.x, v.y), pack_half2(v.z, v.w));
    }
#pragma unroll
    for (int it = 0; it < 2; ++it)
        *(uint4*)&Bs[0][bn_r + it * 64][bseg * 8] = pb[it];
    __syncthreads();

#pragma unroll 2
    for (int ch = 0; ch < 16; ++ch) {
        const int cur = ch & 1, nxt = cur ^ 1;
        if (ch < 15) {
            const int k0 = (ch + 1) * 32;
#pragma unroll
            for (int it = 0; it < 4; ++it)
                pa[it] = *(const float4*)&A[(size_t)(bm + am + it * 32) * 512 + k0 + akq * 4];
#pragma unroll
            for (int it = 0; it < 2; ++it)
                pb[it] = *(const uint4*)&Bt[(size_t)(bn + bn_r + it * 64) * 512 + k0 + bseg * 8];
        }

#pragma unroll
        for (int ks = 0; ks < 2; ++ks) {
            const int k16 = ks * 16;
            uint32_t afr[4][4], bfr[4][2];
#pragma unroll
            for (int mt = 0; mt < 4; ++mt)
                ldsm_x4(afr[mt][0], afr[mt][1], afr[mt][2], afr[mt][3],
                        smem_u32(&As[cur][wm + mt * 16 + (lane & 15)][k16 + (lane >> 4) * 8]));
#pragma unroll
            for (int g = 0; g < 2; ++g) {
                uint32_t b0, b1, b2, b3;
                ldsm_x4(b0, b1, b2, b3,
                        smem_u32(&Bs[cur][wn + g * 16 + (lane & 15)][k16 + (lane >> 4) * 8]));
                bfr[2 * g][0] = b0;     bfr[2 * g][1] = b2;
                bfr[2 * g + 1][0] = b1; bfr[2 * g + 1][1] = b3;
            }
#pragma unroll
            for (int mt = 0; mt < 4; ++mt)
#pragma unroll
                for (int nt = 0; nt < 4; ++nt)
                    mma_f16(acc[mt][nt], afr[mt], bfr[nt]);
        }

        if (ch < 15) {
#pragma unroll
            for (int it = 0; it < 4; ++it) {
                float4 v = pa[it];
                *(uint2*)&As[nxt][am + it * 32][akq * 4] =
                    make_uint2(pack_half2(v.x, v.y), pack_half2(v.z, v.w));
            }
#pragma unroll
            for (int it = 0; it < 2; ++it)
                *(uint4*)&Bs[nxt][bn_r + it * 64][bseg * 8] = pb[it];
        }
        __syncthreads();
    }

    const int r = lane >> 2, c = lane & 3;
#pragma unroll
    for (int mt = 0; mt < 4; ++mt) {
#pragma unroll
        for (int nt = 0; nt < 4; ++nt) {
            int row0 = bm + wm + mt * 16 + r;
            int col  = bn + wn + nt * 8 + 2 * c;
            if (HALF_OUT) {
                __half* C = (__half*)Cv;
                *(__half2*)&C[(size_t)row0 * 512 + col] =
                    __floats2half2_rn(acc[mt][nt][0], acc[mt][nt][1]);
                *(__half2*)&C[(size_t)(row0 + 8) * 512 + col] =
                    __floats2half2_rn(acc[mt][nt][2], acc[mt][nt][3]);
            } else {
                float* C = (float*)Cv;
                *(float2*)&C[(size_t)row0 * 512 + col] =
                    make_float2(acc[mt][nt][0], acc[mt][nt][1]);
                *(float2*)&C[(size_t)(row0 + 8) * 512 + col] =
                    make_float2(acc[mt][nt][2], acc[mt][nt][3]);
            }
        }
    }
}

__global__ __launch_bounds__(256) void qkv_gemm_kernel(
        const float* __restrict__ states, const float* __restrict__ key_states) {
    const float* A; const __half* Bt; __half* C;
    if (blockIdx.z == 0)      { A = states;     Bt = g_wqt; C = g_qh; }
    else if (blockIdx.z == 1) { A = key_states; Bt = g_wkt; C = g_kh; }
    else                      { A = key_states; Bt = g_wvt; C = g_vh; }
    gemm_body<true>(A, Bt, C, blockIdx.x * 128, blockIdx.y * 128);
}

__global__ __launch_bounds__(256) void out_gemm_kernel(float* __restrict__ out) {
    gemm_body<false>(g_ctx, g_wot, out, blockIdx.x * 128, blockIdx.y * 128);
}

// -------------------- prep: transpose + convert weights ---------------------
__global__ void transpose_cvt_kernel(const float* __restrict__ wq,
                                     const float* __restrict__ wk,
                                     const float* __restrict__ wv,
                                     const float* __restrict__ wo) {
    const float* in; __half* out;
    switch (blockIdx.z) {
        case 0:  in = wq; out = g_wqt; break;
        case 1:  in = wk; out = g_wkt; break;
        case 2:  in = wv; out = g_wvt; break;
        default: in = wo; out = g_wot; break;
    }
    __shared__ float t[32][33];
    int tx = threadIdx.x, ty = threadIdx.y;
    int bx = blockIdx.x * 32, by = blockIdx.y * 32;
#pragma unroll
    for (int i = 0; i < 4; ++i)
        t[ty + 8 * i][tx] = in[(size_t)(by + ty + 8 * i) * D_ + bx + tx];
    __syncthreads();
#pragma unroll
    for (int i = 0; i < 4; ++i)
        out[(size_t)(bx + ty + 8 * i) * D_ + by + tx] =
            __float2half_rn(t[tx][ty + 8 * i]);
}

// -------------------- fused bias table + scatter-add ------------------------
__global__ void scatter_bias_kernel(const int* __restrict__ ab,
                                    const float* __restrict__ embs,
                                    const float* __restrict__ scal,
                                    float* __restrict__ bias_mat) {
    __shared__ float table[8];
    int tid = threadIdx.x;
    int e = tid >> 5, lane = tid & 31;
    {
        float s = embs[e * DH_ + lane] * scal[lane]
                + embs[e * DH_ + 32 + lane] * scal[32 + lane];
#pragma unroll
        for (int off = 16; off; off >>= 1) s += __shfl_xor_sync(0xffffffffu, s, off);
        if (lane == 0) table[e] = s;
    }
    __syncthreads();
    int i = blockIdx.x * 256 + tid;
    if (i < E_) {
        int et = ab[i * 4 + 0];
        int b  = ab[i * 4 + 1];
        int qi = ab[i * 4 + 2];
        int ki = ab[i * 4 + 3];
        atomicAdd(&bias_mat[((size_t)b * N_ + qi) * N_ + ki], table[et]);
    }
}

// -------------------- fused causal attention: mma.sync + ldmatrix -----------
// flat grid 512 blocks (qt descending), 128 threads = 4 warps.
// summed_keys computed in-block from the staged K tile.
#define QP 72
__global__ __launch_bounds__(128) void attn_kernel(
        const float* __restrict__ bias_mat, float* __restrict__ ctx) {
    __shared__ __half Qs[64][QP];
    __shared__ __half Ks[64][QP];
    __shared__ __half Vs[64][QP];
    __shared__ float  bsk[64];

    const int bid = blockIdx.x;
    const int qt = 7 - (bid >> 6);
    const int h = (bid >> 3) & 7, b = bid & 7;
    const int tid = threadIdx.x, lane = tid & 31, warp = tid >> 5;
    const int r4 = lane >> 2, t4 = lane & 3;

#pragma unroll
    for (int it = 0; it < 4; ++it) {
        int idx = tid + it * 128;
        int row = idx >> 3, seg = idx & 7;
        *(uint4*)&Qs[row][seg * 8] =
            *(const uint4*)&g_qh[(size_t)(b * N_ + qt * 64 + row) * D_ + h * DH_ + seg * 8];
    }
    __syncthreads();

    uint32_t qf[4][4];
    {
        int lrow = lane & 15, lcol = (lane >> 4) * 8;
#pragma unroll
        for (int ks = 0; ks < 4; ++ks)
            ldsm_x4(qf[ks][0], qf[ks][1], qf[ks][2], qf[ks][3],
                    smem_u32(&Qs[warp * 16 + lrow][ks * 16 + lcol]));
    }

    float m1 = -3.0e38f, m2 = -3.0e38f, l1 = 0.f, l2 = 0.f;
    float o[8][4];
#pragma unroll
    for (int dt = 0; dt < 8; ++dt)
#pragma unroll
        for (int i = 0; i < 4; ++i) o[dt][i] = 0.f;

    const int qg1 = qt * 64 + warp * 16 + r4;
    const int qg2 = qg1 + 8;
    const float* bp1 = bias_mat + (size_t)(b * N_ + qg1) * N_;
    const float* bp2 = bias_mat + (size_t)(b * N_ + qg2) * N_;

    for (int kt = 0; kt <= qt; ++kt) {
        if (kt) __syncthreads();
        if (tid < 64) bsk[tid] = 0.f;
        __syncwarp();
        // stage K/V tiles; accumulate K row-sums into bsk
#pragma unroll
        for (int it = 0; it < 4; ++it) {
            int idx = tid + it * 128;
            int row = idx >> 3, seg = idx & 7;
            size_t g = (size_t)(b * N_ + kt * 64 + row) * D_ + h * DH_ + seg * 8;
            uint4 kq = *(const uint4*)&g_kh[g];
            *(uint4*)&Ks[row][seg * 8] = kq;
            *(uint4*)&Vs[row][seg * 8] = *(const uint4*)&g_vh[g];
            const __half2* hp = (const __half2*)&kq;
            float2 f0 = __half22float2(hp[0]), f1 = __half22float2(hp[1]);
            float2 f2 = __half22float2(hp[2]), f3 = __half22float2(hp[3]);
            atomicAdd(&bsk[row], (f0.x + f0.y) + (f1.x + f1.y)
                               + (f2.x + f2.y) + (f3.x + f3.y));
        }
        __syncthreads();

        float s[8][4];
#pragma unroll
        for (int nt = 0; nt < 8; ++nt) {
#pragma unroll
            for (int i = 0; i < 4; ++i) s[nt][i] = 0.f;
#pragma unroll
            for (int ks = 0; ks < 4; ++ks) {
                uint32_t bf[2];
                ldsm_x2(bf[0], bf[1],
                        smem_u32(&Ks[nt * 8 + (lane & 7)][ks * 16 + ((lane >> 3) & 1) * 8]));
                mma_f16(s[nt], qf[ks], bf);
            }
        }

        float tm1 = -3.0e38f, tm2 = -3.0e38f;
#pragma unroll
        for (int nt = 0; nt < 8; ++nt) {
            int kl = nt * 8 + 2 * t4;
            int kg = kt * 64 + kl;
            float2 bv1 = *(const float2*)&bp1[kg];
            float2 bv2 = *(const float2*)&bp2[kg];
            float s0 = bsk[kl], s1 = bsk[kl + 1];
            s[nt][0] = (kg     <= qg1) ? (s[nt][0] + bv1.x * s0) * 0.125f : -3.0e38f;
            s[nt][1] = (kg + 1 <= qg1) ? (s[nt][1] + bv1.y * s1) * 0.125f : -3.0e38f;
            s[nt][2] = (kg     <= qg2) ? (s[nt][2] + bv2.x * s0) * 0.125f : -3.0e38f;
            s[nt][3] = (kg + 1 <= qg2) ? (s[nt][3] + bv2.y * s1) * 0.125f : -3.0e38f;
            tm1 = fmaxf(tm1, fmaxf(s[nt][0], s[nt][1]));
            tm2 = fmaxf(tm2, fmaxf(s[nt][2], s[nt][3]));
        }
        tm1 = fmaxf(tm1, __shfl_xor_sync(0xffffffffu, tm1, 1));
        tm1 = fmaxf(tm1, __shfl_xor_sync(0xffffffffu, tm1, 2));
        tm2 = fmaxf(tm2, __shfl_xor_sync(0xffffffffu, tm2, 1));
        tm2 = fmaxf(tm2, __shfl_xor_sync(0xffffffffu, tm2, 2));

        float mn1 = fmaxf(m1, tm1), mn2 = fmaxf(m2, tm2);
        float c1 = __expf(m1 - mn1), c2 = __expf(m2 - mn2);
        float sum1 = 0.f, sum2 = 0.f;
#pragma unroll
        for (int nt = 0; nt < 8; ++nt) {
            s[nt][0] = __expf(s[nt][0] - mn1);
            s[nt][1] = __expf(s[nt][1] - mn1);
            s[nt][2] = __expf(s[nt][2] - mn2);
            s[nt][3] = __expf(s[nt][3] - mn2);
            sum1 += s[nt][0] + s[nt][1];
            sum2 += s[nt][2] + s[nt][3];
        }
        sum1 += __shfl_xor_sync(0xffffffffu, sum1, 1);
        sum1 += __shfl_xor_sync(0xffffffffu, sum1, 2);
        sum2 += __shfl_xor_sync(0xffffffffu, sum2, 1);
        sum2 += __shfl_xor_sync(0xffffffffu, sum2, 2);
        l1 = l1 * c1 + sum1; m1 = mn1;
        l2 = l2 * c2 + sum2; m2 = mn2;
#pragma unroll
        for (int dt = 0; dt < 8; ++dt) {
            o[dt][0] *= c1; o[dt][1] *= c1;
            o[dt][2] *= c2; o[dt][3] *= c2;
        }

        uint32_t pf[4][4];
#pragma unroll
        for (int kst = 0; kst < 4; ++kst) {
            pf[kst][0] = pack_half2(s[2 * kst][0],     s[2 * kst][1]);
            pf[kst][1] = pack_half2(s[2 * kst][2],     s[2 * kst][3]);
            pf[kst][2] = pack_half2(s[2 * kst + 1][0], s[2 * kst + 1][1]);
            pf[kst][3] = pack_half2(s[2 * kst + 1][2], s[2 * kst + 1][3]);
        }

#pragma unroll
        for (int g = 0; g < 4; ++g) {
#pragma unroll
            for (int kst = 0; kst < 4; ++kst) {
                uint32_t b0, b1, b2, b3;
                ldsm_x4t(b0, b1, b2, b3,
                         smem_u32(&Vs[kst * 16 + (lane & 15)][g * 16 + (lane >> 4) * 8]));
                uint32_t bfa[2] = {b0, b1}, bfb[2] = {b2, b3};
                mma_f16(o[2 * g],     pf[kst], bfa);
                mma_f16(o[2 * g + 1], pf[kst], bfb);
            }
        }
    }

    float inv1 = 1.0f / l1, inv2 = 1.0f / l2;
#pragma unroll
    for (int dt = 0; dt < 8; ++dt) {
        int col = h * DH_ + dt * 8 + 2 * t4;
        *(float2*)&ctx[(size_t)(b * N_ + qg1) * D_ + col] =
            make_float2(o[dt][0] * inv1, o[dt][1] * inv1);
        *(float2*)&ctx[(size_t)(b * N_ + qg2) * D_ + col] =
            make_float2(o[dt][2] * inv2, o[dt][3] * inv2);
    }
}

// -------------------- launch -------------------------------------------------
extern "C" void kernel_launch(void* const* d_in, const int* in_sizes, int n_in,
                              void* d_out, int out_size) {
    const float* states     = (const float*)d_in[0];
    const float* key_states = (const float*)d_in[1];
    const int*   ab         = (const int*)d_in[3];
    const float* Wq         = (const float*)d_in[4];
    const float* Wk         = (const float*)d_in[5];
    const float* Wv         = (const float*)d_in[6];
    const float* Wo         = (const float*)d_in[7];
    const float* bias_embs  = (const float*)d_in[8];
    const float* bias_scal  = (const float*)d_in[9];
    float* out = (float*)d_out;

    float *gbias, *gctx;
    cudaGetSymbolAddress((void**)&gbias, g_bias);
    cudaGetSymbolAddress((void**)&gctx,  g_ctx);

    // weight transpose + fp16 convert
    dim3 tg(D_ / 32, D_ / 32, 4);
    transpose_cvt_kernel<<<tg, dim3(32, 8)>>>(Wq, Wk, Wv, Wo);

    // bias matrix (independent of projections)
    cudaMemsetAsync(gbias, 0, sizeof(float) * B_ * N_ * N_, 0);
    scatter_bias_kernel<<<(E_ + 255) / 256, 256>>>(ab, bias_embs, bias_scal, gbias);

    // QKV projections
    dim3 qkvgrid(BN_ / 128, D_ / 128, 3);
    qkv_gemm_kernel<<<qkvgrid, 256>>>(states, key_states);

    attn_kernel<<<512, 128>>>(gbias, gctx);

    dim3 ogrid(BN_ / 128, D_ / 128);
    out_gemm_kernel<<<ogrid, 256>>>(out);
}

// round 12
// speedup vs baseline: 4.9767x; 1.2159x over previous
#include <cuda_runtime.h>
#include <cuda_fp16.h>
#include <cstdint>
#include <math.h>

#define B_  8
#define N_  512
#define D_  512
#define H_  8
#define DH_ 64
#define E_  32768
#define BN_ (B_ * N_)          // 4096 rows

// -------------------- scratch (device globals) -----------------------------
__device__ __half g_qh[BN_ * D_];
__device__ __half g_kh[BN_ * D_];
__device__ __half g_vh[BN_ * D_];
__device__ float  g_ctx[BN_ * D_];
__device__ float  g_bias[B_ * N_ * N_];
__device__ __half g_wqt[D_ * D_];   // W^T fp16, [n][k]
__device__ __half g_wkt[D_ * D_];
__device__ __half g_wvt[D_ * D_];
__device__ __half g_wot[D_ * D_];

// -------------------- helpers ----------------------------------------------
__device__ __forceinline__ uint32_t smem_u32(const void* p) {
    uint32_t a;
    asm("{ .reg .u64 t; cvta.to.shared.u64 t, %1; cvt.u32.u64 %0, t; }"
        : "=r"(a) : "l"(p));
    return a;
}
__device__ __forceinline__ uint32_t pack_half2(float x, float y) {
    __half2 h = __floats2half2_rn(x, y);
    return *(uint32_t*)&h;
}
__device__ __forceinline__ void mma_f16(float* d, const uint32_t* a, const uint32_t* b) {
    asm volatile(
        "mma.sync.aligned.m16n8k16.row.col.f32.f16.f16.f32 "
        "{%0,%1,%2,%3}, {%4,%5,%6,%7}, {%8,%9}, {%0,%1,%2,%3};\n"
        : "+f"(d[0]), "+f"(d[1]), "+f"(d[2]), "+f"(d[3])
        : "r"(a[0]), "r"(a[1]), "r"(a[2]), "r"(a[3]), "r"(b[0]), "r"(b[1]));
}
__device__ __forceinline__ void ldsm_x4(uint32_t& r0, uint32_t& r1,
                                        uint32_t& r2, uint32_t& r3, uint32_t a) {
    asm volatile("ldmatrix.sync.aligned.m8n8.x4.shared.b16 {%0,%1,%2,%3}, [%4];"
                 : "=r"(r0), "=r"(r1), "=r"(r2), "=r"(r3) : "r"(a));
}
__device__ __forceinline__ void ldsm_x2(uint32_t& r0, uint32_t& r1, uint32_t a) {
    asm volatile("ldmatrix.sync.aligned.m8n8.x2.shared.b16 {%0,%1}, [%2];"
                 : "=r"(r0), "=r"(r1) : "r"(a));
}
__device__ __forceinline__ void ldsm_x4t(uint32_t& r0, uint32_t& r1,
                                         uint32_t& r2, uint32_t& r3, uint32_t a) {
    asm volatile("ldmatrix.sync.aligned.m8n8.x4.trans.shared.b16 {%0,%1,%2,%3}, [%4];"
                 : "=r"(r0), "=r"(r1), "=r"(r2), "=r"(r3) : "r"(a));
}
__device__ __forceinline__ void cp16(uint32_t s, const void* g) {
    asm volatile("cp.async.cg.shared.global [%0], [%1], 16;" :: "r"(s), "l"(g));
}
__device__ __forceinline__ void cp_commit() {
    asm volatile("cp.async.commit_group;" ::: "memory");
}
__device__ __forceinline__ void cp_wait0() {
    asm volatile("cp.async.wait_group 0;" ::: "memory");
}

// -------------------- fp16 tensor-core GEMM (double-buffered) ---------------
// C[4096,512] = A[4096,512](f32) * Bt^T, Bt fp16 [n][k]. K fixed 512.
// Block 128x128, KB=32, 256 threads = 8 warps (2m x 4n), warp 64x32.
#define GP 40
template <bool HALF_OUT>
__device__ __forceinline__ void gemm_body(const float* __restrict__ A,
                                          const __half* __restrict__ Bt,
                                          void* __restrict__ Cv,
                                          int bm, int bn) {
    __shared__ __half As[2][128][GP];   // [m][k]
    __shared__ __half Bs[2][128][GP];   // [n][k]

    const int tid  = threadIdx.x;
    const int lane = tid & 31;
    const int wid  = tid >> 5;
    const int wm   = (wid & 1) * 64;
    const int wn   = (wid >> 1) * 32;

    float acc[4][4][4];
#pragma unroll
    for (int mt = 0; mt < 4; ++mt)
#pragma unroll
        for (int nt = 0; nt < 4; ++nt)
#pragma unroll
            for (int i = 0; i < 4; ++i) acc[mt][nt][i] = 0.f;

    const int am = tid >> 3, akq = tid & 7;
    const int bn_r = tid >> 2, bseg = tid & 3;

    float4 pa[4];
    uint4  pb[2];
#pragma unroll
    for (int it = 0; it < 4; ++it)
        pa[it] = *(const float4*)&A[(size_t)(bm + am + it * 32) * 512 + akq * 4];
#pragma unroll
    for (int it = 0; it < 2; ++it)
        pb[it] = *(const uint4*)&Bt[(size_t)(bn + bn_r + it * 64) * 512 + bseg * 8];
#pragma unroll
    for (int it = 0; it < 4; ++it) {
        float4 v = pa[it];
        *(uint2*)&As[0][am + it * 32][akq * 4] =
            make_uint2(pack_half2(v.x, v.y), pack_half2(v.z, v.w));
    }
#pragma unroll
    for (int it = 0; it < 2; ++it)
        *(uint4*)&Bs[0][bn_r + it * 64][bseg * 8] = pb[it];
    __syncthreads();

#pragma unroll 2
    for (int ch = 0; ch < 16; ++ch) {
        const int cur = ch & 1, nxt = cur ^ 1;
        if (ch < 15) {
            const int k0 = (ch + 1) * 32;
#pragma unroll
            for (int it = 0; it < 4; ++it)
                pa[it] = *(const float4*)&A[(size_t)(bm + am + it * 32) * 512 + k0 + akq * 4];
#pragma unroll
            for (int it = 0; it < 2; ++it)
                pb[it] = *(const uint4*)&Bt[(size_t)(bn + bn_r + it * 64) * 512 + k0 + bseg * 8];
        }

#pragma unroll
        for (int ks = 0; ks < 2; ++ks) {
            const int k16 = ks * 16;
            uint32_t afr[4][4], bfr[4][2];
#pragma unroll
            for (int mt = 0; mt < 4; ++mt)
                ldsm_x4(afr[mt][0], afr[mt][1], afr[mt][2], afr[mt][3],
                        smem_u32(&As[cur][wm + mt * 16 + (lane & 15)][k16 + (lane >> 4) * 8]));
#pragma unroll
            for (int g = 0; g < 2; ++g) {
                uint32_t b0, b1, b2, b3;
                ldsm_x4(b0, b1, b2, b3,
                        smem_u32(&Bs[cur][wn + g * 16 + (lane & 15)][k16 + (lane >> 4) * 8]));
                bfr[2 * g][0] = b0;     bfr[2 * g][1] = b2;
                bfr[2 * g + 1][0] = b1; bfr[2 * g + 1][1] = b3;
            }
#pragma unroll
            for (int mt = 0; mt < 4; ++mt)
#pragma unroll
                for (int nt = 0; nt < 4; ++nt)
                    mma_f16(acc[mt][nt], afr[mt], bfr[nt]);
        }

        if (ch < 15) {
#pragma unroll
            for (int it = 0; it < 4; ++it) {
                float4 v = pa[it];
                *(uint2*)&As[nxt][am + it * 32][akq * 4] =
                    make_uint2(pack_half2(v.x, v.y), pack_half2(v.z, v.w));
            }
#pragma unroll
            for (int it = 0; it < 2; ++it)
                *(uint4*)&Bs[nxt][bn_r + it * 64][bseg * 8] = pb[it];
        }
        __syncthreads();
    }

    const int r = lane >> 2, c = lane & 3;
#pragma unroll
    for (int mt = 0; mt < 4; ++mt) {
#pragma unroll
        for (int nt = 0; nt < 4; ++nt) {
            int row0 = bm + wm + mt * 16 + r;
            int col  = bn + wn + nt * 8 + 2 * c;
            if (HALF_OUT) {
                __half* C = (__half*)Cv;
                *(__half2*)&C[(size_t)row0 * 512 + col] =
                    __floats2half2_rn(acc[mt][nt][0], acc[mt][nt][1]);
                *(__half2*)&C[(size_t)(row0 + 8) * 512 + col] =
                    __floats2half2_rn(acc[mt][nt][2], acc[mt][nt][3]);
            } else {
                float* C = (float*)Cv;
                *(float2*)&C[(size_t)row0 * 512 + col] =
                    make_float2(acc[mt][nt][0], acc[mt][nt][1]);
                *(float2*)&C[(size_t)(row0 + 8) * 512 + col] =
                    make_float2(acc[mt][nt][2], acc[mt][nt][3]);
            }
        }
    }
}

__global__ __launch_bounds__(256) void qkv_gemm_kernel(
        const float* __restrict__ states, const float* __restrict__ key_states) {
    const float* A; const __half* Bt; __half* C;
    if (blockIdx.z == 0)      { A = states;     Bt = g_wqt; C = g_qh; }
    else if (blockIdx.z == 1) { A = key_states; Bt = g_wkt; C = g_kh; }
    else                      { A = key_states; Bt = g_wvt; C = g_vh; }
    gemm_body<true>(A, Bt, C, blockIdx.x * 128, blockIdx.y * 128);
}

__global__ __launch_bounds__(256) void out_gemm_kernel(float* __restrict__ out) {
    gemm_body<false>(g_ctx, g_wot, out, blockIdx.x * 128, blockIdx.y * 128);
}

// -------------------- prep: transpose + convert weights ---------------------
__global__ void transpose_cvt_kernel(const float* __restrict__ wq,
                                     const float* __restrict__ wk,
                                     const float* __restrict__ wv,
                                     const float* __restrict__ wo) {
    const float* in; __half* out;
    switch (blockIdx.z) {
        case 0:  in = wq; out = g_wqt; break;
        case 1:  in = wk; out = g_wkt; break;
        case 2:  in = wv; out = g_wvt; break;
        default: in = wo; out = g_wot; break;
    }
    __shared__ float t[32][33];
    int tx = threadIdx.x, ty = threadIdx.y;
    int bx = blockIdx.x * 32, by = blockIdx.y * 32;
#pragma unroll
    for (int i = 0; i < 4; ++i)
        t[ty + 8 * i][tx] = in[(size_t)(by + ty + 8 * i) * D_ + bx + tx];
    __syncthreads();
#pragma unroll
    for (int i = 0; i < 4; ++i)
        out[(size_t)(bx + ty + 8 * i) * D_ + by + tx] =
            __float2half_rn(t[tx][ty + 8 * i]);
}

// -------------------- fused bias table + scatter-add ------------------------
__global__ void scatter_bias_kernel(const int* __restrict__ ab,
                                    const float* __restrict__ embs,
                                    const float* __restrict__ scal,
                                    float* __restrict__ bias_mat) {
    __shared__ float table[8];
    int tid = threadIdx.x;
    int e = tid >> 5, lane = tid & 31;
    {
        float s = embs[e * DH_ + lane] * scal[lane]
                + embs[e * DH_ + 32 + lane] * scal[32 + lane];
#pragma unroll
        for (int off = 16; off; off >>= 1) s += __shfl_xor_sync(0xffffffffu, s, off);
        if (lane == 0) table[e] = s;
    }
    __syncthreads();
    int i = blockIdx.x * 256 + tid;
    if (i < E_) {
        int et = ab[i * 4 + 0];
        int b  = ab[i * 4 + 1];
        int qi = ab[i * 4 + 2];
        int ki = ab[i * 4 + 3];
        atomicAdd(&bias_mat[((size_t)b * N_ + qi) * N_ + ki], table[et]);
    }
}

// -------------------- fused causal attention: cp.async pipelined ------------
// flat grid 512 blocks (qt descending), 128 threads = 4 warps.
#define QP 72
__global__ __launch_bounds__(128) void attn_kernel(
        const float* __restrict__ bias_mat, float* __restrict__ ctx) {
    __shared__ __half Qs[64][QP];
    __shared__ __half Ks[2][64][QP];
    __shared__ __half Vs[2][64][QP];
    __shared__ float  bsk[64];

    const int bid = blockIdx.x;
    const int qt = 7 - (bid >> 6);
    const int h = (bid >> 3) & 7, b = bid & 7;
    const int tid = threadIdx.x, lane = tid & 31, warp = tid >> 5;
    const int r4 = lane >> 2, t4 = lane & 3;

    // chunk mapping for K/V staging: 512 16B-chunks per tile, 4 per thread
    const int srow = tid >> 3, sseg = tid & 7;   // +16 rows per it

    // prologue: async-stage K/V tile kt=0
#pragma unroll
    for (int it = 0; it < 4; ++it) {
        int row = srow + it * 16;
        size_t g = (size_t)(b * N_ + row) * D_ + h * DH_ + sseg * 8;
        cp16(smem_u32(&Ks[0][row][sseg * 8]), &g_kh[g]);
        cp16(smem_u32(&Vs[0][row][sseg * 8]), &g_vh[g]);
    }
    cp_commit();

    // stage Q tile
#pragma unroll
    for (int it = 0; it < 4; ++it) {
        int row = srow + it * 16;
        *(uint4*)&Qs[row][sseg * 8] =
            *(const uint4*)&g_qh[(size_t)(b * N_ + qt * 64 + row) * D_ + h * DH_ + sseg * 8];
    }
    __syncthreads();

    uint32_t qf[4][4];
    {
        int lrow = lane & 15, lcol = (lane >> 4) * 8;
#pragma unroll
        for (int ks = 0; ks < 4; ++ks)
            ldsm_x4(qf[ks][0], qf[ks][1], qf[ks][2], qf[ks][3],
                    smem_u32(&Qs[warp * 16 + lrow][ks * 16 + lcol]));
    }

    float m1 = -3.0e38f, m2 = -3.0e38f, l1 = 0.f, l2 = 0.f;
    float o[8][4];
#pragma unroll
    for (int dt = 0; dt < 8; ++dt)
#pragma unroll
        for (int i = 0; i < 4; ++i) o[dt][i] = 0.f;

    const int qg1 = qt * 64 + warp * 16 + r4;
    const int qg2 = qg1 + 8;
    const float* bp1 = bias_mat + (size_t)(b * N_ + qg1) * N_;
    const float* bp2 = bias_mat + (size_t)(b * N_ + qg2) * N_;

    for (int kt = 0; kt <= qt; ++kt) {
        const int cur = kt & 1;
        cp_wait0();
        __syncthreads();   // staged data visible; prior reads of nxt buffer done

        // prefetch next tile (overlaps with everything below)
        if (kt < qt) {
            const int nxt = cur ^ 1;
#pragma unroll
            for (int it = 0; it < 4; ++it) {
                int row = srow + it * 16;
                size_t g = (size_t)(b * N_ + (kt + 1) * 64 + row) * D_ + h * DH_ + sseg * 8;
                cp16(smem_u32(&Ks[nxt][row][sseg * 8]), &g_kh[g]);
                cp16(smem_u32(&Vs[nxt][row][sseg * 8]), &g_vh[g]);
            }
            cp_commit();
        }

        // summed_keys for this tile from staged Ks (2 threads per row,
        // 32 halves = 4 uint4 each)
        {
            int rr = tid >> 1, hh = tid & 1;
            const uint4* p = (const uint4*)&Ks[cur][rr][hh * 32];
            float s = 0.f;
#pragma unroll
            for (int i = 0; i < 4; ++i) {
                uint4 v = p[i];
                const __half2* hp = (const __half2*)&v;
#pragma unroll
                for (int j = 0; j < 4; ++j) {
                    float2 f = __half22float2(hp[j]);
                    s += f.x + f.y;
                }
            }
            s += __shfl_xor_sync(0xffffffffu, s, 1);
            if (!hh) bsk[rr] = s;
        }
        __syncthreads();

        float s[8][4];
#pragma unroll
        for (int nt = 0; nt < 8; ++nt) {
#pragma unroll
            for (int i = 0; i < 4; ++i) s[nt][i] = 0.f;
#pragma unroll
            for (int ks = 0; ks < 4; ++ks) {
                uint32_t bf[2];
                ldsm_x2(bf[0], bf[1],
                        smem_u32(&Ks[cur][nt * 8 + (lane & 7)][ks * 16 + ((lane >> 3) & 1) * 8]));
                mma_f16(s[nt], qf[ks], bf);
            }
        }

        float tm1 = -3.0e38f, tm2 = -3.0e38f;
#pragma unroll
        for (int nt = 0; nt < 8; ++nt) {
            int kl = nt * 8 + 2 * t4;
            int kg = kt * 64 + kl;
            float2 bv1 = *(const float2*)&bp1[kg];
            float2 bv2 = *(const float2*)&bp2[kg];
            float s0 = bsk[kl], s1 = bsk[kl + 1];
            s[nt][0] = (kg     <= qg1) ? (s[nt][0] + bv1.x * s0) * 0.125f : -3.0e38f;
            s[nt][1] = (kg + 1 <= qg1) ? (s[nt][1] + bv1.y * s1) * 0.125f : -3.0e38f;
            s[nt][2] = (kg     <= qg2) ? (s[nt][2] + bv2.x * s0) * 0.125f : -3.0e38f;
            s[nt][3] = (kg + 1 <= qg2) ? (s[nt][3] + bv2.y * s1) * 0.125f : -3.0e38f;
            tm1 = fmaxf(tm1, fmaxf(s[nt][0], s[nt][1]));
            tm2 = fmaxf(tm2, fmaxf(s[nt][2], s[nt][3]));
        }
        tm1 = fmaxf(tm1, __shfl_xor_sync(0xffffffffu, tm1, 1));
        tm1 = fmaxf(tm1, __shfl_xor_sync(0xffffffffu, tm1, 2));
        tm2 = fmaxf(tm2, __shfl_xor_sync(0xffffffffu, tm2, 1));
        tm2 = fmaxf(tm2, __shfl_xor_sync(0xffffffffu, tm2, 2));

        float mn1 = fmaxf(m1, tm1), mn2 = fmaxf(m2, tm2);
        float c1 = __expf(m1 - mn1), c2 = __expf(m2 - mn2);
        float sum1 = 0.f, sum2 = 0.f;
#pragma unroll
        for (int nt = 0; nt < 8; ++nt) {
            s[nt][0] = __expf(s[nt][0] - mn1);
            s[nt][1] = __expf(s[nt][1] - mn1);
            s[nt][2] = __expf(s[nt][2] - mn2);
            s[nt][3] = __expf(s[nt][3] - mn2);
            sum1 += s[nt][0] + s[nt][1];
            sum2 += s[nt][2] + s[nt][3];
        }
        sum1 += __shfl_xor_sync(0xffffffffu, sum1, 1);
        sum1 += __shfl_xor_sync(0xffffffffu, sum1, 2);
        sum2 += __shfl_xor_sync(0xffffffffu, sum2, 1);
        sum2 += __shfl_xor_sync(0xffffffffu, sum2, 2);
        l1 = l1 * c1 + sum1; m1 = mn1;
        l2 = l2 * c2 + sum2; m2 = mn2;
#pragma unroll
        for (int dt = 0; dt < 8; ++dt) {
            o[dt][0] *= c1; o[dt][1] *= c1;
            o[dt][2] *= c2; o[dt][3] *= c2;
        }

        uint32_t pf[4][4];
#pragma unroll
        for (int kst = 0; kst < 4; ++kst) {
            pf[kst][0] = pack_half2(s[2 * kst][0],     s[2 * kst][1]);
            pf[kst][1] = pack_half2(s[2 * kst][2],     s[2 * kst][3]);
            pf[kst][2] = pack_half2(s[2 * kst + 1][0], s[2 * kst + 1][1]);
            pf[kst][3] = pack_half2(s[2 * kst + 1][2], s[2 * kst + 1][3]);
        }

#pragma unroll
        for (int g = 0; g < 4; ++g) {
#pragma unroll
            for (int kst = 0; kst < 4; ++kst) {
                uint32_t b0, b1, b2, b3;
                ldsm_x4t(b0, b1, b2, b3,
                         smem_u32(&Vs[cur][kst * 16 + (lane & 15)][g * 16 + (lane >> 4) * 8]));
                uint32_t bfa[2] = {b0, b1}, bfb[2] = {b2, b3};
                mma_f16(o[2 * g],     pf[kst], bfa);
                mma_f16(o[2 * g + 1], pf[kst], bfb);
            }
        }
    }

    float inv1 = 1.0f / l1, inv2 = 1.0f / l2;
#pragma unroll
    for (int dt = 0; dt < 8; ++dt) {
        int col = h * DH_ + dt * 8 + 2 * t4;
        *(float2*)&ctx[(size_t)(b * N_ + qg1) * D_ + col] =
            make_float2(o[dt][0] * inv1, o[dt][1] * inv1);
        *(float2*)&ctx[(size_t)(b * N_ + qg2) * D_ + col] =
            make_float2(o[dt][2] * inv2, o[dt][3] * inv2);
    }
}

// -------------------- launch -------------------------------------------------
extern "C" void kernel_launch(void* const* d_in, const int* in_sizes, int n_in,
                              void* d_out, int out_size) {
    const float* states     = (const float*)d_in[0];
    const float* key_states = (const float*)d_in[1];
    const int*   ab         = (const int*)d_in[3];
    const float* Wq         = (const float*)d_in[4];
    const float* Wk         = (const float*)d_in[5];
    const float* Wv         = (const float*)d_in[6];
    const float* Wo         = (const float*)d_in[7];
    const float* bias_embs  = (const float*)d_in[8];
    const float* bias_scal  = (const float*)d_in[9];
    float* out = (float*)d_out;

    float *gbias, *gctx;
    cudaGetSymbolAddress((void**)&gbias, g_bias);
    cudaGetSymbolAddress((void**)&gctx,  g_ctx);

    // weight transpose + fp16 convert
    dim3 tg(D_ / 32, D_ / 32, 4);
    transpose_cvt_kernel<<<tg, dim3(32, 8)>>>(Wq, Wk, Wv, Wo);

    // bias matrix
    cudaMemsetAsync(gbias, 0, sizeof(float) * B_ * N_ * N_, 0);
    scatter_bias_kernel<<<(E_ + 255) / 256, 256>>>(ab, bias_embs, bias_scal, gbias);

    // QKV projections
    dim3 qkvgrid(BN_ / 128, D_ / 128, 3);
    qkv_gemm_kernel<<<qkvgrid, 256>>>(states, key_states);

    attn_kernel<<<512, 128>>>(gbias, gctx);

    dim3 ogrid(BN_ / 128, D_ / 128);
    out_gemm_kernel<<<ogrid, 256>>>(out);
}